// round 13
// baseline (speedup 1.0000x reference)
#include <cuda_runtime.h>
#include <cuda_fp16.h>
#include <stdint.h>
#include <math.h>

// ---------------- problem constants ----------------
#define NB      2
#define TLEN    1024
#define DMODEL  512
#define DIN     1024
#define DTRANK  64
#define DSTATE  16
#define NPROJ   96

#define R0 2048
#define R1 1024
#define R2 512
#define RSUM (R0+R1+R2)

#define LOG2E 1.4426950408889634f
#define LN2   0.6931471805599453f

// ---------------- fp32 scratch ----------------
__device__ float g_proj [RSUM*NPROJ];
__device__ float g_fused[R0*DIN];
__device__ float g_pre  [R0*DMODEL];

// ---------------- fp16 planes ----------------
__device__ __half g_xh  [R0*DMODEL];
__device__ __half g_wih [2*DIN*DMODEL];
__device__ __half g_xph [3*NPROJ*DIN];
__device__ __half g_dwh [3*DIN*DTRANK];
__device__ __half g_c1h [(DIN/2)*DIN];
__device__ __half g_c2h [DIN*(DIN/2)];
__device__ __half g_owh [DMODEL*DIN];
__device__ __half g_xzH [R0*2*DIN];
__device__ __half g_xs1H[R1*DIN];
__device__ __half g_xs2H[R2*DIN];
__device__ __half g_xcH [RSUM*DIN];
__device__ __half g_dtH [RSUM*DIN];
__device__ __half g_pH  [RSUM*NPROJ];
__device__ __half g_yH  [RSUM*DIN];
__device__ __half g_cth [R0*DIN];
__device__ __half g_h1h [R0*(DIN/2)];
__device__ __half g_ach [R0*DIN];

// ---------------- math helpers (MUFU-based) ----------------
__device__ __forceinline__ float ex2a(float x) {
    float y;
    asm("ex2.approx.f32 %0, %1;" : "=f"(y) : "f"(x));
    return y;
}
__device__ __forceinline__ float lg2a(float x) {
    float y;
    asm("lg2.approx.f32 %0, %1;" : "=f"(y) : "f"(x));
    return y;
}
__device__ __forceinline__ float sigmoidf_(float x) {
    return __fdividef(1.0f, 1.0f + ex2a(-x * LOG2E));
}
__device__ __forceinline__ float siluf_(float x) { return x * sigmoidf_(x); }
__device__ __forceinline__ float softplusf_(float x) {
    float u = ex2a(-fabsf(x) * LOG2E);
    return fmaxf(x, 0.0f) + lg2a(1.0f + u) * LN2;
}

// ---------------- convert inputs/weights into fp16 planes ----------------
#define SEG0 (R0*DMODEL)
#define SEG1 (2*DIN*DMODEL)
#define SEG2 (3*NPROJ*DIN)
#define SEG3 (3*DIN*DTRANK)
#define SEG4 ((DIN/2)*DIN)
#define SEG5 (DIN*(DIN/2))
#define SEG6 (DMODEL*DIN)
#define CU0 (SEG0)
#define CU1 (CU0+SEG1)
#define CU2 (CU1+SEG2)
#define CU3 (CU2+SEG3)
#define CU4 (CU3+SEG4)
#define CU5 (CU4+SEG5)
#define CU6 (CU5+SEG6)

__global__ void split_all(const float* __restrict__ x,
                          const float* __restrict__ w1,
                          const float* __restrict__ w2,
                          const float* __restrict__ w3,
                          const float* __restrict__ w4,
                          const float* __restrict__ w5,
                          const float* __restrict__ w6)
{
    long i = ((long)blockIdx.x * blockDim.x + threadIdx.x) * 4;
    if (i >= CU6) return;
    const float* src; __half* dh; long off;
    if      (i < CU0) { src=x;  dh=g_xh;  off=0;   }
    else if (i < CU1) { src=w1; dh=g_wih; off=CU0; }
    else if (i < CU2) { src=w2; dh=g_xph; off=CU1; }
    else if (i < CU3) { src=w3; dh=g_dwh; off=CU2; }
    else if (i < CU4) { src=w4; dh=g_c1h; off=CU3; }
    else if (i < CU5) { src=w5; dh=g_c2h; off=CU4; }
    else              { src=w6; dh=g_owh; off=CU5; }
    long j = i - off;
    float4 v = *(const float4*)(src + j);
    *(__half2*)(dh + j)     = __floats2half2_rn(v.x, v.y);
    *(__half2*)(dh + j + 2) = __floats2half2_rn(v.z, v.w);
}

// ---------------- 5-stage pipelined tensor-core GEMM (pure fp16) ----------------
#define ASTR 40
#define APL (128*ASTR)
#define BPL (64*ASTR)
#define STG (APL + BPL)
#define NSTAGE 5
#define SMEM_BYTES (NSTAGE*STG*2)

__device__ __forceinline__ void ldm_x4(unsigned int* r, const __half* p) {
    unsigned int a = (unsigned int)__cvta_generic_to_shared(p);
    asm volatile("ldmatrix.sync.aligned.m8n8.x4.shared.b16 {%0,%1,%2,%3}, [%4];"
                 : "=r"(r[0]), "=r"(r[1]), "=r"(r[2]), "=r"(r[3]) : "r"(a));
}
__device__ __forceinline__ void mma16816(float* c, const unsigned int* a,
                                         const unsigned int* b) {
    asm volatile(
        "mma.sync.aligned.m16n8k16.row.col.f32.f16.f16.f32 "
        "{%0,%1,%2,%3}, {%4,%5,%6,%7}, {%8,%9}, {%0,%1,%2,%3};"
        : "+f"(c[0]), "+f"(c[1]), "+f"(c[2]), "+f"(c[3])
        : "r"(a[0]), "r"(a[1]), "r"(a[2]), "r"(a[3]), "r"(b[0]), "r"(b[1]));
}
__device__ __forceinline__ void cp16(unsigned int dst, const void* src, bool pred) {
    int sz = pred ? 16 : 0;
    asm volatile("cp.async.cg.shared.global [%0], [%1], 16, %2;\n"
                 :: "r"(dst), "l"(src), "r"(sz));
}

// mode: 0 none | 1 +bias | 2 silu | 3 sigmoid(acc)*e1f*silu(e2h) | 4 +e1f
__global__ void __launch_bounds__(256, 2) gemm_f16(
    const __half* __restrict__ Ahi, int lda,
    const __half* __restrict__ Whi, int ldb, int wstride,
    float* Cf, __half* Chi, int ldc,
    int4 Ms, int4 rowoffs, int N, int K,
    const float* bias, int bstride, int mode,
    const float* e1, int lde1, const __half* e2h, int lde2)
{
    extern __shared__ __align__(16) __half sm[];
    const int z = blockIdx.z;
    const int M      = (z == 0) ? Ms.x      : ((z == 1) ? Ms.y      : Ms.z);
    const int rowoff = (z == 0) ? rowoffs.x : ((z == 1) ? rowoffs.y : rowoffs.z);
    const int m0 = blockIdx.y * 128;
    if (m0 >= M) return;
    const int n0 = blockIdx.x * 64;

    const int tid = threadIdx.x, lane = tid & 31, wid = tid >> 5;
    const int wm = wid & 3, wn = wid >> 2;

    const __half* Ah = Ahi + (size_t)rowoff * lda;
    const __half* Wh = Whi + (size_t)z * wstride;

    const int arow = tid >> 1, acol = (tid & 1) * 16;
    const int brow = tid >> 2, bcol = (tid & 3) * 8;
    const bool bv = (n0 + brow) < N;

    const __half* agh = Ah + (size_t)(m0 + arow) * lda + acol;
    const __half* bgh = Wh + (size_t)(n0 + brow) * ldb + bcol;

    unsigned int sbase = (unsigned int)__cvta_generic_to_shared(sm);
    const int a_dst = arow * ASTR + acol;
    const int b_dst = brow * ASTR + bcol;

    float acc[2][4][4];
    #pragma unroll
    for (int i = 0; i < 2; i++)
        #pragma unroll
        for (int j = 0; j < 4; j++)
            #pragma unroll
            for (int r = 0; r < 4; r++) acc[i][j][r] = 0.0f;

    const int aoff = (wm * 32 + (lane & 15)) * ASTR + (lane >> 4) * 8;
    const int boff = (wn * 32 + ((lane >> 4) << 3) + (lane & 7)) * ASTR
                   + ((lane >> 3) & 1) * 8;

    const int nk = K / 32;

    auto issue = [&](int s) {
        int k0 = s * 32;
        unsigned int st = sbase + (unsigned int)(s % NSTAGE) * (STG * 2);
        cp16(st + (a_dst) * 2,       agh + k0,     true);
        cp16(st + (a_dst + 8) * 2,   agh + k0 + 8, true);
        cp16(st + (APL + b_dst) * 2, bgh + k0,     bv);
    };

    #pragma unroll
    for (int s = 0; s < NSTAGE - 1; s++) {
        if (s < nk) issue(s);
        asm volatile("cp.async.commit_group;\n");
    }

    for (int it = 0; it < nk; it++) {
        asm volatile("cp.async.wait_group %0;\n" :: "n"(NSTAGE - 2));
        __syncthreads();

        int pf = it + NSTAGE - 1;
        if (pf < nk) issue(pf);
        asm volatile("cp.async.commit_group;\n");

        const __half* st = sm + (it % NSTAGE) * STG;
        #pragma unroll
        for (int k16 = 0; k16 < 2; k16++) {
            unsigned int ahif[8];
            unsigned int bhif[8];
            const __half* pa = st + aoff + k16 * 16;
            ldm_x4(&ahif[0], pa);
            ldm_x4(&ahif[4], pa + 16 * ASTR);
            const __half* pb = st + APL + boff + k16 * 16;
            ldm_x4(&bhif[0], pb);
            ldm_x4(&bhif[4], pb + 16 * ASTR);
            #pragma unroll
            for (int mi = 0; mi < 2; mi++) {
                #pragma unroll
                for (int ni = 0; ni < 4; ni++) {
                    mma16816(acc[mi][ni], &ahif[mi * 4], &bhif[ni * 2]);
                }
            }
        }
    }

    // ---- epilogue ----
    #pragma unroll
    for (int mi = 0; mi < 2; mi++) {
        #pragma unroll
        for (int ni = 0; ni < 4; ni++) {
            int mb = m0 + wm * 32 + mi * 16 + (lane >> 2);
            int nb = n0 + wn * 32 + ni * 8 + (lane & 3) * 2;
            #pragma unroll
            for (int r = 0; r < 4; r++) {
                int mloc = mb + ((r >> 1) << 3);
                int n = nb + (r & 1);
                if (n >= N) continue;
                int m = rowoff + mloc;
                float v = acc[mi][ni][r];
                if (mode == 1)      v += bias[z * bstride + n];
                else if (mode == 2) v = siluf_(v);
                else if (mode == 3) v = sigmoidf_(v) * e1[(size_t)m * lde1 + n]
                                  * siluf_(__half2float(e2h[(size_t)m * lde2 + n]));
                else if (mode == 4) v += e1[(size_t)m * lde1 + n];
                size_t o = (size_t)m * ldc + n;
                if (Cf)  Cf[o] = v;
                if (Chi) Chi[o] = __float2half(v);
            }
        }
    }
}

// ---------------- downsample (both scales, one launch; fp16, half2) ----------------
__global__ void down_batched()
{
    int z = blockIdx.y + 1;                 // 1 or 2
    int Tout = TLEN >> z;
    int S = 1 << z;
    float invS = 1.0f / S;
    int total = NB * Tout * (DIN / 2);
    int idx = blockIdx.x * blockDim.x + threadIdx.x;
    if (idx >= total) return;
    int d2 = idx & (DIN/2 - 1);
    int t  = (idx / (DIN/2)) % Tout;
    int b  = idx / (Tout * (DIN/2));
    const __half* p = g_xzH + (size_t)(b * TLEN + t * S) * (2 * DIN) + d2 * 2;
    float sx = 0.f, sy = 0.f;
    #pragma unroll 4
    for (int r = 0; r < S; r++) {
        float2 a = __half22float2(*(const __half2*)(p + (size_t)r * 2 * DIN));
        sx += a.x; sy += a.y;
    }
    __half* dst = (z == 1) ? g_xs1H : g_xs2H;
    *(__half2*)(dst + (size_t)idx * 2) = __floats2half2_rn(sx * invS, sy * invS);
}

// ---------------- depthwise causal conv, temporal-blocked x4, half2 channels ----------------
// Each thread: 2 adjacent channels x 4 consecutive timesteps.
__global__ void conv_batched(const float* __restrict__ cw,
                             const float* __restrict__ cb)
{
    int z = blockIdx.y;
    int Tl = TLEN >> z;
    int T4 = Tl >> 2;
    int total = NB * T4 * (DIN / 2);
    int idx = blockIdx.x * blockDim.x + threadIdx.x;
    if (idx >= total) return;
    const __half* xin = (z == 0) ? g_xzH : ((z == 1) ? g_xs1H : g_xs2H);
    int ldx = (z == 0) ? 2 * DIN : DIN;
    size_t roff = (z == 0) ? 0 : ((z == 1) ? (size_t)R0 * DIN : (size_t)(R0 + R1) * DIN);

    int d2 = idx & (DIN/2 - 1);
    int t4 = (idx / (DIN/2)) % T4;
    int b  = idx / (T4 * (DIN/2));
    int d  = d2 * 2;
    int t0 = t4 * 4;

    const float4 w0 = *(const float4*)(cw + (size_t)z * DIN * 4 + d * 4);
    const float4 w1 = *(const float4*)(cw + (size_t)z * DIN * 4 + d * 4 + 4);
    const float2 bi = *(const float2*)(cb + (size_t)z * DIN + d);
    float wa[4]; wa[0]=w0.x; wa[1]=w0.y; wa[2]=w0.z; wa[3]=w0.w;
    float wb[4]; wb[0]=w1.x; wb[1]=w1.y; wb[2]=w1.z; wb[3]=w1.w;

    const __half* base = xin + (size_t)(b * Tl) * ldx + d;
    float2 in[7];
    #pragma unroll
    for (int k = 0; k < 7; k++) {
        int tt = t0 + k - 3;
        in[k] = (tt >= 0)
              ? __half22float2(*(const __half2*)(base + (size_t)tt * ldx))
              : make_float2(0.f, 0.f);
    }

    __half* outp = g_xcH + roff + (size_t)(b * Tl + t0) * DIN + d;
    #pragma unroll
    for (int q = 0; q < 4; q++) {
        float ax = bi.x, ay = bi.y;
        #pragma unroll
        for (int k = 0; k < 4; k++) {
            float2 v = in[q + k];
            ax = fmaf(wa[k], v.x, ax);
            ay = fmaf(wb[k], v.y, ay);
        }
        *(__half2*)(outp + (size_t)q * DIN) = __floats2half2_rn(siluf_(ax), siluf_(ay));
    }
}

// ---------------- selective scan, batched (MUFU exp, fp16 y output) ----------------
__global__ void scan_batched(const float* __restrict__ A_log,
                             const float* __restrict__ Dp)
{
    const int z = blockIdx.y;
    const int Tl = TLEN >> z;
    const size_t roff  = (z == 0) ? 0 : ((z == 1) ? (size_t)R0 : (size_t)(R0 + R1));
    const __half* xc   = g_xcH + roff * DIN;
    const float*  proj = g_proj + roff * NPROJ;
    const __half* dt   = g_dtH + roff * DIN;
    __half*       y    = g_yH  + roff * DIN;
    const float*  Al   = A_log + z * DIN * DSTATE;
    const float*  Dz   = Dp + z * DIN;

    const int j    = threadIdx.x & 15;
    const int dloc = threadIdx.x >> 4;
    const int b    = blockIdx.x >> 6;
    const int d0   = (blockIdx.x & 63) * 16;
    const int d    = d0 + dloc;

    __shared__ float2 s_ddx[64][16];   // (softplus(dt), dt*xc)
    __shared__ float2 s_BC [64][16];   // (B, C)
    __shared__ float  s_xc [64][16];

    const float Aj2 = -expf(Al[d * 16 + j]) * LOG2E;
    const float Dv  = Dz[d];
    float h = 0.0f;

    for (int t0 = 0; t0 < Tl; t0 += 64) {
        for (int i = threadIdx.x; i < 64 * 8; i += 256) {
            int tt = i >> 3, dl2 = i & 7;
            int dl = dl2 * 2;
            size_t rbase = (size_t)(b * Tl + t0 + tt);
            float2 dtv2 = __half22float2(*(const __half2*)(dt + rbase * DIN + d0 + dl));
            float2 xcv2 = __half22float2(*(const __half2*)(xc + rbase * DIN + d0 + dl));
            float sp0 = softplusf_(dtv2.x), sp1 = softplusf_(dtv2.y);
            s_ddx[tt][dl]   = make_float2(sp0, sp0 * xcv2.x);
            s_ddx[tt][dl+1] = make_float2(sp1, sp1 * xcv2.y);
            s_xc[tt][dl]   = xcv2.x;
            s_xc[tt][dl+1] = xcv2.y;
            const float* pr = proj + rbase * NPROJ;
            float2 Bv = *(const float2*)(pr + DTRANK + dl);
            float2 Cv = *(const float2*)(pr + DTRANK + DSTATE + dl);
            s_BC[tt][dl]   = make_float2(Bv.x, Cv.x);
            s_BC[tt][dl+1] = make_float2(Bv.y, Cv.y);
        }
        __syncthreads();
        #pragma unroll 4
        for (int tt = 0; tt < 64; tt++) {
            float2 ddx = s_ddx[tt][dloc];
            float2 bc  = s_BC[tt][j];
            float dA  = ex2a(ddx.x * Aj2);                 // in (0,1]; underflow==clamp
            float dBx = fmaxf(ddx.y * bc.x, 1e-38f);
            h = fmaf(dA, h, dBx);
            float part = bc.y * h;
            part += __shfl_xor_sync(0xffffffffu, part, 8);
            part += __shfl_xor_sync(0xffffffffu, part, 4);
            part += __shfl_xor_sync(0xffffffffu, part, 2);
            part += __shfl_xor_sync(0xffffffffu, part, 1);
            if (j == 0)
                y[(size_t)(b * Tl + t0 + tt) * DIN + d] =
                    __float2half(fmaf(Dv, s_xc[tt][dloc], part));
        }
        __syncthreads();
    }
}

// ---------------- fuse (half2 y reads, includes scale-weight softmax) ----------------
__global__ void fuse_kernel(const float* __restrict__ sw)
{
    int idx4 = blockIdx.x * blockDim.x + threadIdx.x;   // 4-element units
    int d4 = idx4 & (DIN/4 - 1);
    int t  = (idx4 / (DIN/4)) & (TLEN - 1);
    int b  = idx4 / ((DIN/4) * TLEN);
    int d  = d4 * 4;

    float a = sw[0], bb = sw[1], c = sw[2];
    float mx = fmaxf(a, fmaxf(bb, c));
    float ea = ex2a((a - mx) * LOG2E);
    float eb = ex2a((bb - mx) * LOG2E);
    float ec = ex2a((c - mx) * LOG2E);
    float inv = __fdividef(1.0f, ea + eb + ec);
    ea *= inv; eb *= inv; ec *= inv;

    size_t i0 = (size_t)(b * TLEN + t) * DIN + d;
    size_t i1 = (size_t)R0 * DIN + (size_t)(b * (TLEN/2) + (t >> 1)) * DIN + d;
    size_t i2 = (size_t)(R0 + R1) * DIN + (size_t)(b * (TLEN/4) + (t >> 2)) * DIN + d;
    float2 o0a = __half22float2(*(const __half2*)(g_yH + i0));
    float2 o0b = __half22float2(*(const __half2*)(g_yH + i0 + 2));
    float2 o1a = __half22float2(*(const __half2*)(g_yH + i1));
    float2 o1b = __half22float2(*(const __half2*)(g_yH + i1 + 2));
    float2 o2a = __half22float2(*(const __half2*)(g_yH + i2));
    float2 o2b = __half22float2(*(const __half2*)(g_yH + i2 + 2));

    float4 f;
    f.x = ea*o0a.x + eb*o1a.x + ec*o2a.x;
    f.y = ea*o0a.y + eb*o1a.y + ec*o2a.y;
    f.z = ea*o0b.x + eb*o1b.x + ec*o2b.x;
    f.w = ea*o0b.y + eb*o1b.y + ec*o2b.y;
    *(float4*)(g_fused + i0) = f;

    const float th = 1.0f / 3.0f;
    *(__half2*)(g_cth + i0)     = __floats2half2_rn((o0a.x+o1a.x+o2a.x)*th,
                                                    (o0a.y+o1a.y+o2a.y)*th);
    *(__half2*)(g_cth + i0 + 2) = __floats2half2_rn((o0b.x+o1b.x+o2b.x)*th,
                                                    (o0b.y+o1b.y+o2b.y)*th);
}

// ---------------- LayerNorm ----------------
__global__ void ln_kernel(const float* __restrict__ gamma,
                          const float* __restrict__ beta,
                          float* __restrict__ out)
{
    int row = blockIdx.x;
    int tid = threadIdx.x;
    const float* r = g_pre + (size_t)row * DMODEL;
    float v1 = r[tid], v2 = r[tid + 256];
    float s  = v1 + v2;
    float q  = v1 * v1 + v2 * v2;
    #pragma unroll
    for (int o = 16; o > 0; o >>= 1) {
        s += __shfl_xor_sync(0xffffffffu, s, o);
        q += __shfl_xor_sync(0xffffffffu, q, o);
    }
    __shared__ float sh[8], sh2[8];
    int wid = tid >> 5, lane = tid & 31;
    if (lane == 0) { sh[wid] = s; sh2[wid] = q; }
    __syncthreads();
    if (tid == 0) {
        float ts = 0.f, tq = 0.f;
        #pragma unroll
        for (int i = 0; i < 8; i++) { ts += sh[i]; tq += sh2[i]; }
        sh[0] = ts; sh2[0] = tq;
    }
    __syncthreads();
    float mu  = sh[0] * (1.0f / DMODEL);
    float var = sh2[0] * (1.0f / DMODEL) - mu * mu;
    float inv = rsqrtf(var + 1e-5f);
    float* o = out + (size_t)row * DMODEL;
    o[tid]       = (v1 - mu) * inv * gamma[tid]       + beta[tid];
    o[tid + 256] = (v2 - mu) * inv * gamma[tid + 256] + beta[tid + 256];
}

// ---------------- driver ----------------
extern "C" void kernel_launch(void* const* d_in, const int* in_sizes, int n_in,
                              void* d_out, int out_size)
{
    const float* x        = (const float*)d_in[0];
    const float* in_proj  = (const float*)d_in[1];
    const float* conv_w   = (const float*)d_in[2];
    const float* conv_b   = (const float*)d_in[3];
    const float* xproj_w  = (const float*)d_in[4];
    const float* dtproj_w = (const float*)d_in[5];
    const float* dtproj_b = (const float*)d_in[6];
    const float* A_log    = (const float*)d_in[7];
    const float* D_p      = (const float*)d_in[8];
    const float* sw       = (const float*)d_in[9];
    const float* cg_w1    = (const float*)d_in[10];
    const float* cg_w2    = (const float*)d_in[11];
    const float* out_w    = (const float*)d_in[12];
    const float* ln_g     = (const float*)d_in[13];
    const float* ln_b     = (const float*)d_in[14];
    float* out            = (float*)d_out;

    static bool attr_set = false;
    if (!attr_set) {
        cudaFuncSetAttribute(gemm_f16, cudaFuncAttributeMaxDynamicSharedMemorySize,
                             SMEM_BYTES);
        attr_set = true;
    }

    float *proj, *fused, *pre;
    __half *xh,*wih,*xph,*dwh,*c1h,*c2h,*owh;
    __half *xzH,*xcH,*dtH,*pH,*cth,*h1h,*ach;
    cudaGetSymbolAddress((void**)&proj, g_proj);
    cudaGetSymbolAddress((void**)&fused,g_fused);
    cudaGetSymbolAddress((void**)&pre,  g_pre);
    cudaGetSymbolAddress((void**)&xh,  g_xh);
    cudaGetSymbolAddress((void**)&wih, g_wih);
    cudaGetSymbolAddress((void**)&xph, g_xph);
    cudaGetSymbolAddress((void**)&dwh, g_dwh);
    cudaGetSymbolAddress((void**)&c1h, g_c1h);
    cudaGetSymbolAddress((void**)&c2h, g_c2h);
    cudaGetSymbolAddress((void**)&owh, g_owh);
    cudaGetSymbolAddress((void**)&xzH, g_xzH);
    cudaGetSymbolAddress((void**)&xcH, g_xcH);
    cudaGetSymbolAddress((void**)&dtH, g_dtH);
    cudaGetSymbolAddress((void**)&pH,  g_pH);
    cudaGetSymbolAddress((void**)&cth, g_cth);
    cudaGetSymbolAddress((void**)&h1h, g_h1h);
    cudaGetSymbolAddress((void**)&ach, g_ach);

    const int4 M1   = make_int4(R0, 0, 0, 0);
    const int4 OFF0 = make_int4(0, 0, 0, 0);
    const int4 M3   = make_int4(R0, R1, R2, 0);
    const int4 OFF3 = make_int4(0, R0, R0 + R1, 0);

    // 0. convert inputs + weights to fp16 planes
    split_all<<<(CU6/4 + 255)/256, 256>>>(x, in_proj, xproj_w, dtproj_w,
                                          cg_w1, cg_w2, out_w);

    // 1. in_proj -> fp16 xz
    gemm_f16<<<dim3(32, 16, 1), 256, SMEM_BYTES>>>(
        xh, DMODEL, wih, DMODEL, 0,
        nullptr, xzH, 2*DIN, M1, OFF0, 2*DIN, DMODEL,
        nullptr, 0, 0, nullptr, 0, nullptr, 0);

    // 2. downsample (both scales, one launch)
    down_batched<<<dim3((R1*DIN/2 + 255)/256, 2), 256>>>();

    // 3. conv (temporal-blocked x4, half2 channels)
    conv_batched<<<dim3((R0*DIN/8 + 255)/256, 3), 256>>>(conv_w, conv_b);

    // 4. xproj (batched): N=96, K=1024
    gemm_f16<<<dim3(2, 16, 3), 256, SMEM_BYTES>>>(
        xcH, DIN, xph, DIN, NPROJ*DIN,
        proj, pH, NPROJ, M3, OFF3, NPROJ, DIN,
        nullptr, 0, 0, nullptr, 0, nullptr, 0);

    // 5. dtproj (batched): N=1024, K=64 (+bias) -> fp16 dt
    gemm_f16<<<dim3(16, 16, 3), 256, SMEM_BYTES>>>(
        pH, NPROJ, dwh, DTRANK, DIN*DTRANK,
        nullptr, dtH, DIN, M3, OFF3, DIN, DTRANK,
        dtproj_b, DIN, 1, nullptr, 0, nullptr, 0);

    // 6. selective scan (batched)
    scan_batched<<<dim3(128, 3), 256>>>(A_log, D_p);

    // 7. fuse (+softmax)
    fuse_kernel<<<(R0*DIN/4)/256, 256>>>(sw);

    // 8. context gate
    gemm_f16<<<dim3(8, 16, 1), 256, SMEM_BYTES>>>(
        cth, DIN, c1h, DIN, 0,
        nullptr, h1h, DIN/2, M1, OFF0, DIN/2, DIN,
        nullptr, 0, 2, nullptr, 0, nullptr, 0);
    gemm_f16<<<dim3(16, 16, 1), 256, SMEM_BYTES>>>(
        h1h, DIN/2, c2h, DIN/2, 0,
        nullptr, ach, DIN, M1, OFF0, DIN, DIN/2,
        nullptr, 0, 3, fused, DIN, xzH + DIN, 2*DIN);

    // 9. out_proj + residual
    gemm_f16<<<dim3(8, 16, 1), 256, SMEM_BYTES>>>(
        ach, DIN, owh, DIN, 0,
        pre, nullptr, DMODEL, M1, OFF0, DMODEL, DIN,
        nullptr, 0, 4, x, DMODEL, nullptr, 0);

    // 10. LayerNorm
    ln_kernel<<<R0, 256>>>(ln_g, ln_b, out);
}

// round 14
// speedup vs baseline: 1.8100x; 1.8100x over previous
#include <cuda_runtime.h>
#include <cuda_fp16.h>
#include <stdint.h>
#include <math.h>

// ---------------- problem constants ----------------
#define NB      2
#define TLEN    1024
#define DMODEL  512
#define DIN     1024
#define DTRANK  64
#define DSTATE  16
#define NPROJ   96

#define R0 2048
#define R1 1024
#define R2 512
#define RSUM (R0+R1+R2)

#define LOG2E 1.4426950408889634f
#define LN2   0.6931471805599453f

// ---------------- fp32 scratch ----------------
__device__ float g_proj [RSUM*NPROJ];
__device__ float g_y    [RSUM*DIN];
__device__ float g_fused[R0*DIN];
__device__ float g_pre  [R0*DMODEL];

// ---------------- fp16 planes ----------------
__device__ __half g_xh  [R0*DMODEL];
__device__ __half g_wih [2*DIN*DMODEL];
__device__ __half g_xph [3*NPROJ*DIN];
__device__ __half g_dwh [3*DIN*DTRANK];
__device__ __half g_c1h [(DIN/2)*DIN];
__device__ __half g_c2h [DIN*(DIN/2)];
__device__ __half g_owh [DMODEL*DIN];
__device__ __half g_xzH [R0*2*DIN];
__device__ __half g_xs1H[R1*DIN];
__device__ __half g_xs2H[R2*DIN];
__device__ __half g_xcH [RSUM*DIN];
__device__ __half g_dtH [RSUM*DIN];
__device__ __half g_pH  [RSUM*NPROJ];
__device__ __half g_cth [R0*DIN];
__device__ __half g_h1h [R0*(DIN/2)];
__device__ __half g_ach [R0*DIN];

// ---------------- math helpers (MUFU-based) ----------------
__device__ __forceinline__ float ex2a(float x) {
    float y;
    asm("ex2.approx.f32 %0, %1;" : "=f"(y) : "f"(x));
    return y;
}
__device__ __forceinline__ float lg2a(float x) {
    float y;
    asm("lg2.approx.f32 %0, %1;" : "=f"(y) : "f"(x));
    return y;
}
__device__ __forceinline__ float sigmoidf_(float x) {
    return __fdividef(1.0f, 1.0f + ex2a(-x * LOG2E));
}
__device__ __forceinline__ float siluf_(float x) { return x * sigmoidf_(x); }
__device__ __forceinline__ float softplusf_(float x) {
    float u = ex2a(-fabsf(x) * LOG2E);
    return fmaxf(x, 0.0f) + lg2a(1.0f + u) * LN2;
}

// ---------------- convert inputs/weights into fp16 planes ----------------
#define SEG0 (R0*DMODEL)
#define SEG1 (2*DIN*DMODEL)
#define SEG2 (3*NPROJ*DIN)
#define SEG3 (3*DIN*DTRANK)
#define SEG4 ((DIN/2)*DIN)
#define SEG5 (DIN*(DIN/2))
#define SEG6 (DMODEL*DIN)
#define CU0 (SEG0)
#define CU1 (CU0+SEG1)
#define CU2 (CU1+SEG2)
#define CU3 (CU2+SEG3)
#define CU4 (CU3+SEG4)
#define CU5 (CU4+SEG5)
#define CU6 (CU5+SEG6)

__global__ void split_all(const float* __restrict__ x,
                          const float* __restrict__ w1,
                          const float* __restrict__ w2,
                          const float* __restrict__ w3,
                          const float* __restrict__ w4,
                          const float* __restrict__ w5,
                          const float* __restrict__ w6)
{
    long i = ((long)blockIdx.x * blockDim.x + threadIdx.x) * 4;
    if (i >= CU6) return;
    const float* src; __half* dh; long off;
    if      (i < CU0) { src=x;  dh=g_xh;  off=0;   }
    else if (i < CU1) { src=w1; dh=g_wih; off=CU0; }
    else if (i < CU2) { src=w2; dh=g_xph; off=CU1; }
    else if (i < CU3) { src=w3; dh=g_dwh; off=CU2; }
    else if (i < CU4) { src=w4; dh=g_c1h; off=CU3; }
    else if (i < CU5) { src=w5; dh=g_c2h; off=CU4; }
    else              { src=w6; dh=g_owh; off=CU5; }
    long j = i - off;
    float4 v = *(const float4*)(src + j);
    *(__half2*)(dh + j)     = __floats2half2_rn(v.x, v.y);
    *(__half2*)(dh + j + 2) = __floats2half2_rn(v.z, v.w);
}

// ---------------- 5-stage pipelined tensor-core GEMM (pure fp16) ----------------
#define ASTR 40
#define APL (128*ASTR)
#define BPL (64*ASTR)
#define STG (APL + BPL)
#define NSTAGE 5
#define SMEM_BYTES (NSTAGE*STG*2)

__device__ __forceinline__ void ldm_x4(unsigned int* r, const __half* p) {
    unsigned int a = (unsigned int)__cvta_generic_to_shared(p);
    asm volatile("ldmatrix.sync.aligned.m8n8.x4.shared.b16 {%0,%1,%2,%3}, [%4];"
                 : "=r"(r[0]), "=r"(r[1]), "=r"(r[2]), "=r"(r[3]) : "r"(a));
}
__device__ __forceinline__ void mma16816(float* c, const unsigned int* a,
                                         const unsigned int* b) {
    asm volatile(
        "mma.sync.aligned.m16n8k16.row.col.f32.f16.f16.f32 "
        "{%0,%1,%2,%3}, {%4,%5,%6,%7}, {%8,%9}, {%0,%1,%2,%3};"
        : "+f"(c[0]), "+f"(c[1]), "+f"(c[2]), "+f"(c[3])
        : "r"(a[0]), "r"(a[1]), "r"(a[2]), "r"(a[3]), "r"(b[0]), "r"(b[1]));
}
__device__ __forceinline__ void cp16(unsigned int dst, const void* src, bool pred) {
    int sz = pred ? 16 : 0;
    asm volatile("cp.async.cg.shared.global [%0], [%1], 16, %2;\n"
                 :: "r"(dst), "l"(src), "r"(sz));
}

// mode: 0 none | 1 +bias | 2 silu | 3 sigmoid(acc)*e1f*silu(e2h) | 4 +e1f
__global__ void __launch_bounds__(256, 2) gemm_f16(
    const __half* __restrict__ Ahi, int lda,
    const __half* __restrict__ Whi, int ldb, int wstride,
    float* Cf, __half* Chi, int ldc,
    int4 Ms, int4 rowoffs, int N, int K,
    const float* bias, int bstride, int mode,
    const float* e1, int lde1, const __half* e2h, int lde2)
{
    extern __shared__ __align__(16) __half sm[];
    const int z = blockIdx.z;
    const int M      = (z == 0) ? Ms.x      : ((z == 1) ? Ms.y      : Ms.z);
    const int rowoff = (z == 0) ? rowoffs.x : ((z == 1) ? rowoffs.y : rowoffs.z);
    const int m0 = blockIdx.y * 128;
    if (m0 >= M) return;
    const int n0 = blockIdx.x * 64;

    const int tid = threadIdx.x, lane = tid & 31, wid = tid >> 5;
    const int wm = wid & 3, wn = wid >> 2;

    const __half* Ah = Ahi + (size_t)rowoff * lda;
    const __half* Wh = Whi + (size_t)z * wstride;

    const int arow = tid >> 1, acol = (tid & 1) * 16;
    const int brow = tid >> 2, bcol = (tid & 3) * 8;
    const bool bv = (n0 + brow) < N;

    const __half* agh = Ah + (size_t)(m0 + arow) * lda + acol;
    const __half* bgh = Wh + (size_t)(n0 + brow) * ldb + bcol;

    unsigned int sbase = (unsigned int)__cvta_generic_to_shared(sm);
    const int a_dst = arow * ASTR + acol;
    const int b_dst = brow * ASTR + bcol;

    float acc[2][4][4];
    #pragma unroll
    for (int i = 0; i < 2; i++)
        #pragma unroll
        for (int j = 0; j < 4; j++)
            #pragma unroll
            for (int r = 0; r < 4; r++) acc[i][j][r] = 0.0f;

    const int aoff = (wm * 32 + (lane & 15)) * ASTR + (lane >> 4) * 8;
    const int boff = (wn * 32 + ((lane >> 4) << 3) + (lane & 7)) * ASTR
                   + ((lane >> 3) & 1) * 8;

    const int nk = K / 32;

    auto issue = [&](int s) {
        int k0 = s * 32;
        unsigned int st = sbase + (unsigned int)(s % NSTAGE) * (STG * 2);
        cp16(st + (a_dst) * 2,       agh + k0,     true);
        cp16(st + (a_dst + 8) * 2,   agh + k0 + 8, true);
        cp16(st + (APL + b_dst) * 2, bgh + k0,     bv);
    };

    #pragma unroll
    for (int s = 0; s < NSTAGE - 1; s++) {
        if (s < nk) issue(s);
        asm volatile("cp.async.commit_group;\n");
    }

    for (int it = 0; it < nk; it++) {
        asm volatile("cp.async.wait_group %0;\n" :: "n"(NSTAGE - 2));
        __syncthreads();

        int pf = it + NSTAGE - 1;
        if (pf < nk) issue(pf);
        asm volatile("cp.async.commit_group;\n");

        const __half* st = sm + (it % NSTAGE) * STG;
        #pragma unroll
        for (int k16 = 0; k16 < 2; k16++) {
            unsigned int ahif[8];
            unsigned int bhif[8];
            const __half* pa = st + aoff + k16 * 16;
            ldm_x4(&ahif[0], pa);
            ldm_x4(&ahif[4], pa + 16 * ASTR);
            const __half* pb = st + APL + boff + k16 * 16;
            ldm_x4(&bhif[0], pb);
            ldm_x4(&bhif[4], pb + 16 * ASTR);
            #pragma unroll
            for (int mi = 0; mi < 2; mi++) {
                #pragma unroll
                for (int ni = 0; ni < 4; ni++) {
                    mma16816(acc[mi][ni], &ahif[mi * 4], &bhif[ni * 2]);
                }
            }
        }
    }

    // ---- epilogue ----
    #pragma unroll
    for (int mi = 0; mi < 2; mi++) {
        #pragma unroll
        for (int ni = 0; ni < 4; ni++) {
            int mb = m0 + wm * 32 + mi * 16 + (lane >> 2);
            int nb = n0 + wn * 32 + ni * 8 + (lane & 3) * 2;
            #pragma unroll
            for (int r = 0; r < 4; r++) {
                int mloc = mb + ((r >> 1) << 3);
                int n = nb + (r & 1);
                if (n >= N) continue;
                int m = rowoff + mloc;
                float v = acc[mi][ni][r];
                if (mode == 1)      v += bias[z * bstride + n];
                else if (mode == 2) v = siluf_(v);
                else if (mode == 3) v = sigmoidf_(v) * e1[(size_t)m * lde1 + n]
                                  * siluf_(__half2float(e2h[(size_t)m * lde2 + n]));
                else if (mode == 4) v += e1[(size_t)m * lde1 + n];
                size_t o = (size_t)m * ldc + n;
                if (Cf)  Cf[o] = v;
                if (Chi) Chi[o] = __float2half(v);
            }
        }
    }
}

// ---------------- downsample (both scales, one launch; fp16, half2) ----------------
__global__ void down_batched()
{
    int z = blockIdx.y + 1;                 // 1 or 2
    int Tout = TLEN >> z;
    int S = 1 << z;
    float invS = 1.0f / S;
    int total = NB * Tout * (DIN / 2);
    int idx = blockIdx.x * blockDim.x + threadIdx.x;
    if (idx >= total) return;
    int d2 = idx & (DIN/2 - 1);
    int t  = (idx / (DIN/2)) % Tout;
    int b  = idx / (Tout * (DIN/2));
    const __half* p = g_xzH + (size_t)(b * TLEN + t * S) * (2 * DIN) + d2 * 2;
    float sx = 0.f, sy = 0.f;
    #pragma unroll 4
    for (int r = 0; r < S; r++) {
        float2 a = __half22float2(*(const __half2*)(p + (size_t)r * 2 * DIN));
        sx += a.x; sy += a.y;
    }
    __half* dst = (z == 1) ? g_xs1H : g_xs2H;
    *(__half2*)(dst + (size_t)idx * 2) = __floats2half2_rn(sx * invS, sy * invS);
}

// ---------------- depthwise causal conv, temporal-blocked x4, half2 channels ----------------
__global__ void conv_batched(const float* __restrict__ cw,
                             const float* __restrict__ cb)
{
    int z = blockIdx.y;
    int Tl = TLEN >> z;
    int T4 = Tl >> 2;
    int total = NB * T4 * (DIN / 2);
    int idx = blockIdx.x * blockDim.x + threadIdx.x;
    if (idx >= total) return;
    const __half* xin = (z == 0) ? g_xzH : ((z == 1) ? g_xs1H : g_xs2H);
    int ldx = (z == 0) ? 2 * DIN : DIN;
    size_t roff = (z == 0) ? 0 : ((z == 1) ? (size_t)R0 * DIN : (size_t)(R0 + R1) * DIN);

    int d2 = idx & (DIN/2 - 1);
    int t4 = (idx / (DIN/2)) % T4;
    int b  = idx / (T4 * (DIN/2));
    int d  = d2 * 2;
    int t0 = t4 * 4;

    const float4 w0 = *(const float4*)(cw + (size_t)z * DIN * 4 + d * 4);
    const float4 w1 = *(const float4*)(cw + (size_t)z * DIN * 4 + d * 4 + 4);
    const float2 bi = *(const float2*)(cb + (size_t)z * DIN + d);
    float wa[4]; wa[0]=w0.x; wa[1]=w0.y; wa[2]=w0.z; wa[3]=w0.w;
    float wb[4]; wb[0]=w1.x; wb[1]=w1.y; wb[2]=w1.z; wb[3]=w1.w;

    const __half* base = xin + (size_t)(b * Tl) * ldx + d;
    float2 in[7];
    #pragma unroll
    for (int k = 0; k < 7; k++) {
        int tt = t0 + k - 3;
        in[k] = (tt >= 0)
              ? __half22float2(*(const __half2*)(base + (size_t)tt * ldx))
              : make_float2(0.f, 0.f);
    }

    __half* outp = g_xcH + roff + (size_t)(b * Tl + t0) * DIN + d;
    #pragma unroll
    for (int q = 0; q < 4; q++) {
        float ax = bi.x, ay = bi.y;
        #pragma unroll
        for (int k = 0; k < 4; k++) {
            float2 v = in[q + k];
            ax = fmaf(wa[k], v.x, ax);
            ay = fmaf(wb[k], v.y, ay);
        }
        *(__half2*)(outp + (size_t)q * DIN) = __floats2half2_rn(siluf_(ax), siluf_(ay));
    }
}

// ---------------- selective scan, batched (MUFU exp, packed/vectorized smem) ----------------
__global__ void scan_batched(const float* __restrict__ A_log,
                             const float* __restrict__ Dp)
{
    const int z = blockIdx.y;
    const int Tl = TLEN >> z;
    const size_t roff  = (z == 0) ? 0 : ((z == 1) ? (size_t)R0 : (size_t)(R0 + R1));
    const __half* xc   = g_xcH + roff * DIN;
    const float*  proj = g_proj + roff * NPROJ;
    const __half* dt   = g_dtH + roff * DIN;
    float*        y    = g_y   + roff * DIN;
    const float*  Al   = A_log + z * DIN * DSTATE;
    const float*  Dz   = Dp + z * DIN;

    const int j    = threadIdx.x & 15;
    const int dloc = threadIdx.x >> 4;
    const int b    = blockIdx.x >> 6;
    const int d0   = (blockIdx.x & 63) * 16;
    const int d    = d0 + dloc;

    __shared__ float2 s_ddx[64][16];   // (softplus(dt), dt*xc)
    __shared__ float2 s_BC [64][16];   // (B, C)
    __shared__ float  s_xc [64][16];

    const float Aj2 = -expf(Al[d * 16 + j]) * LOG2E;
    const float Dv  = Dz[d];
    float h = 0.0f;

    for (int t0 = 0; t0 < Tl; t0 += 64) {
        for (int i = threadIdx.x; i < 64 * 8; i += 256) {
            int tt = i >> 3, dl2 = i & 7;
            int dl = dl2 * 2;
            size_t rbase = (size_t)(b * Tl + t0 + tt);
            float2 dtv2 = __half22float2(*(const __half2*)(dt + rbase * DIN + d0 + dl));
            float2 xcv2 = __half22float2(*(const __half2*)(xc + rbase * DIN + d0 + dl));
            float sp0 = softplusf_(dtv2.x), sp1 = softplusf_(dtv2.y);
            s_ddx[tt][dl]   = make_float2(sp0, sp0 * xcv2.x);
            s_ddx[tt][dl+1] = make_float2(sp1, sp1 * xcv2.y);
            s_xc[tt][dl]   = xcv2.x;
            s_xc[tt][dl+1] = xcv2.y;
            const float* pr = proj + rbase * NPROJ;
            float2 Bv = *(const float2*)(pr + DTRANK + dl);
            float2 Cv = *(const float2*)(pr + DTRANK + DSTATE + dl);
            s_BC[tt][dl]   = make_float2(Bv.x, Cv.x);
            s_BC[tt][dl+1] = make_float2(Bv.y, Cv.y);
        }
        __syncthreads();
        #pragma unroll 4
        for (int tt = 0; tt < 64; tt++) {
            float2 ddx = s_ddx[tt][dloc];
            float2 bc  = s_BC[tt][j];
            float dA  = fmaxf(ex2a(ddx.x * Aj2), 1e-38f);
            float dBx = fmaxf(ddx.y * bc.x, 1e-38f);
            h = fmaf(dA, h, dBx);
            float part = bc.y * h;
            part += __shfl_xor_sync(0xffffffffu, part, 8);
            part += __shfl_xor_sync(0xffffffffu, part, 4);
            part += __shfl_xor_sync(0xffffffffu, part, 2);
            part += __shfl_xor_sync(0xffffffffu, part, 1);
            if (j == 0)
                y[(size_t)(b * Tl + t0 + tt) * DIN + d] = fmaf(Dv, s_xc[tt][dloc], part);
        }
        __syncthreads();
    }
}

// ---------------- fuse (float4-vectorized, includes scale-weight softmax) ----------------
__global__ void fuse_kernel(const float* __restrict__ sw)
{
    int idx4 = blockIdx.x * blockDim.x + threadIdx.x;   // float4 units
    int d4 = idx4 & (DIN/4 - 1);
    int t  = (idx4 / (DIN/4)) & (TLEN - 1);
    int b  = idx4 / ((DIN/4) * TLEN);
    int d  = d4 * 4;

    float a = sw[0], bb = sw[1], c = sw[2];
    float mx = fmaxf(a, fmaxf(bb, c));
    float ea = ex2a((a - mx) * LOG2E);
    float eb = ex2a((bb - mx) * LOG2E);
    float ec = ex2a((c - mx) * LOG2E);
    float inv = __fdividef(1.0f, ea + eb + ec);
    ea *= inv; eb *= inv; ec *= inv;

    size_t i0 = (size_t)(b * TLEN + t) * DIN + d;
    size_t i1 = (size_t)R0 * DIN + (size_t)(b * (TLEN/2) + (t >> 1)) * DIN + d;
    size_t i2 = (size_t)(R0 + R1) * DIN + (size_t)(b * (TLEN/4) + (t >> 2)) * DIN + d;
    float4 o0 = *(const float4*)(g_y + i0);
    float4 o1 = *(const float4*)(g_y + i1);
    float4 o2 = *(const float4*)(g_y + i2);

    float4 f;
    f.x = ea*o0.x + eb*o1.x + ec*o2.x;
    f.y = ea*o0.y + eb*o1.y + ec*o2.y;
    f.z = ea*o0.z + eb*o1.z + ec*o2.z;
    f.w = ea*o0.w + eb*o1.w + ec*o2.w;
    *(float4*)(g_fused + i0) = f;

    const float th = 1.0f / 3.0f;
    *(__half2*)(g_cth + i0)     = __floats2half2_rn((o0.x+o1.x+o2.x)*th, (o0.y+o1.y+o2.y)*th);
    *(__half2*)(g_cth + i0 + 2) = __floats2half2_rn((o0.z+o1.z+o2.z)*th, (o0.w+o1.w+o2.w)*th);
}

// ---------------- LayerNorm ----------------
__global__ void ln_kernel(const float* __restrict__ gamma,
                          const float* __restrict__ beta,
                          float* __restrict__ out)
{
    int row = blockIdx.x;
    int tid = threadIdx.x;
    const float* r = g_pre + (size_t)row * DMODEL;
    float v1 = r[tid], v2 = r[tid + 256];
    float s  = v1 + v2;
    float q  = v1 * v1 + v2 * v2;
    #pragma unroll
    for (int o = 16; o > 0; o >>= 1) {
        s += __shfl_xor_sync(0xffffffffu, s, o);
        q += __shfl_xor_sync(0xffffffffu, q, o);
    }
    __shared__ float sh[8], sh2[8];
    int wid = tid >> 5, lane = tid & 31;
    if (lane == 0) { sh[wid] = s; sh2[wid] = q; }
    __syncthreads();
    if (tid == 0) {
        float ts = 0.f, tq = 0.f;
        #pragma unroll
        for (int i = 0; i < 8; i++) { ts += sh[i]; tq += sh2[i]; }
        sh[0] = ts; sh2[0] = tq;
    }
    __syncthreads();
    float mu  = sh[0] * (1.0f / DMODEL);
    float var = sh2[0] * (1.0f / DMODEL) - mu * mu;
    float inv = rsqrtf(var + 1e-5f);
    float* o = out + (size_t)row * DMODEL;
    o[tid]       = (v1 - mu) * inv * gamma[tid]       + beta[tid];
    o[tid + 256] = (v2 - mu) * inv * gamma[tid + 256] + beta[tid + 256];
}

// ---------------- driver ----------------
extern "C" void kernel_launch(void* const* d_in, const int* in_sizes, int n_in,
                              void* d_out, int out_size)
{
    const float* x        = (const float*)d_in[0];
    const float* in_proj  = (const float*)d_in[1];
    const float* conv_w   = (const float*)d_in[2];
    const float* conv_b   = (const float*)d_in[3];
    const float* xproj_w  = (const float*)d_in[4];
    const float* dtproj_w = (const float*)d_in[5];
    const float* dtproj_b = (const float*)d_in[6];
    const float* A_log    = (const float*)d_in[7];
    const float* D_p      = (const float*)d_in[8];
    const float* sw       = (const float*)d_in[9];
    const float* cg_w1    = (const float*)d_in[10];
    const float* cg_w2    = (const float*)d_in[11];
    const float* out_w    = (const float*)d_in[12];
    const float* ln_g     = (const float*)d_in[13];
    const float* ln_b     = (const float*)d_in[14];
    float* out            = (float*)d_out;

    static bool attr_set = false;
    if (!attr_set) {
        cudaFuncSetAttribute(gemm_f16, cudaFuncAttributeMaxDynamicSharedMemorySize,
                             SMEM_BYTES);
        attr_set = true;
    }

    float *proj, *fused, *pre;
    __half *xh,*wih,*xph,*dwh,*c1h,*c2h,*owh;
    __half *xzH,*xcH,*dtH,*pH,*cth,*h1h,*ach;
    cudaGetSymbolAddress((void**)&proj, g_proj);
    cudaGetSymbolAddress((void**)&fused,g_fused);
    cudaGetSymbolAddress((void**)&pre,  g_pre);
    cudaGetSymbolAddress((void**)&xh,  g_xh);
    cudaGetSymbolAddress((void**)&wih, g_wih);
    cudaGetSymbolAddress((void**)&xph, g_xph);
    cudaGetSymbolAddress((void**)&dwh, g_dwh);
    cudaGetSymbolAddress((void**)&c1h, g_c1h);
    cudaGetSymbolAddress((void**)&c2h, g_c2h);
    cudaGetSymbolAddress((void**)&owh, g_owh);
    cudaGetSymbolAddress((void**)&xzH, g_xzH);
    cudaGetSymbolAddress((void**)&xcH, g_xcH);
    cudaGetSymbolAddress((void**)&dtH, g_dtH);
    cudaGetSymbolAddress((void**)&pH,  g_pH);
    cudaGetSymbolAddress((void**)&cth, g_cth);
    cudaGetSymbolAddress((void**)&h1h, g_h1h);
    cudaGetSymbolAddress((void**)&ach, g_ach);

    const int4 M1   = make_int4(R0, 0, 0, 0);
    const int4 OFF0 = make_int4(0, 0, 0, 0);
    const int4 M3   = make_int4(R0, R1, R2, 0);
    const int4 OFF3 = make_int4(0, R0, R0 + R1, 0);

    // 0. convert inputs + weights to fp16 planes
    split_all<<<(CU6/4 + 255)/256, 256>>>(x, in_proj, xproj_w, dtproj_w,
                                          cg_w1, cg_w2, out_w);

    // 1. in_proj -> fp16 xz
    gemm_f16<<<dim3(32, 16, 1), 256, SMEM_BYTES>>>(
        xh, DMODEL, wih, DMODEL, 0,
        nullptr, xzH, 2*DIN, M1, OFF0, 2*DIN, DMODEL,
        nullptr, 0, 0, nullptr, 0, nullptr, 0);

    // 2. downsample (both scales, one launch)
    down_batched<<<dim3((R1*DIN/2 + 255)/256, 2), 256>>>();

    // 3. conv (temporal-blocked x4, half2 channels)
    conv_batched<<<dim3((R0*DIN/8 + 255)/256, 3), 256>>>(conv_w, conv_b);

    // 4. xproj (batched): N=96, K=1024
    gemm_f16<<<dim3(2, 16, 3), 256, SMEM_BYTES>>>(
        xcH, DIN, xph, DIN, NPROJ*DIN,
        proj, pH, NPROJ, M3, OFF3, NPROJ, DIN,
        nullptr, 0, 0, nullptr, 0, nullptr, 0);

    // 5. dtproj (batched): N=1024, K=64 (+bias) -> fp16 dt
    gemm_f16<<<dim3(16, 16, 3), 256, SMEM_BYTES>>>(
        pH, NPROJ, dwh, DTRANK, DIN*DTRANK,
        nullptr, dtH, DIN, M3, OFF3, DIN, DTRANK,
        dtproj_b, DIN, 1, nullptr, 0, nullptr, 0);

    // 6. selective scan (batched)
    scan_batched<<<dim3(128, 3), 256>>>(A_log, D_p);

    // 7. fuse (+softmax), float4-vectorized
    fuse_kernel<<<(R0*DIN/4)/256, 256>>>(sw);

    // 8. context gate
    gemm_f16<<<dim3(8, 16, 1), 256, SMEM_BYTES>>>(
        cth, DIN, c1h, DIN, 0,
        nullptr, h1h, DIN/2, M1, OFF0, DIN/2, DIN,
        nullptr, 0, 2, nullptr, 0, nullptr, 0);
    gemm_f16<<<dim3(16, 16, 1), 256, SMEM_BYTES>>>(
        h1h, DIN/2, c2h, DIN/2, 0,
        nullptr, ach, DIN, M1, OFF0, DIN, DIN/2,
        nullptr, 0, 3, fused, DIN, xzH + DIN, 2*DIN);

    // 9. out_proj + residual
    gemm_f16<<<dim3(8, 16, 1), 256, SMEM_BYTES>>>(
        ach, DIN, owh, DIN, 0,
        pre, nullptr, DMODEL, M1, OFF0, DMODEL, DIN,
        nullptr, 0, 4, x, DMODEL, nullptr, 0);

    // 10. LayerNorm
    ln_kernel<<<R0, 256>>>(ln_g, ln_b, out);
}

// round 15
// speedup vs baseline: 1.9029x; 1.0513x over previous
#include <cuda_runtime.h>
#include <cuda_fp16.h>
#include <stdint.h>
#include <math.h>

// ---------------- problem constants ----------------
#define NB      2
#define TLEN    1024
#define DMODEL  512
#define DIN     1024
#define DTRANK  64
#define DSTATE  16
#define NPROJ   96

#define R0 2048
#define R1 1024
#define R2 512
#define RSUM (R0+R1+R2)

#define LOG2E 1.4426950408889634f
#define LN2   0.6931471805599453f

// ---------------- fp32 scratch ----------------
__device__ float g_proj [RSUM*NPROJ];
__device__ float g_y    [RSUM*DIN];
__device__ float g_fused[R0*DIN];
__device__ float g_pre  [R0*DMODEL];

// ---------------- fp16 planes ----------------
__device__ __half g_xh  [R0*DMODEL];
__device__ __half g_wih [2*DIN*DMODEL];
__device__ __half g_xph [3*NPROJ*DIN];
__device__ __half g_dwh [3*DIN*DTRANK];
__device__ __half g_c1h [(DIN/2)*DIN];
__device__ __half g_c2h [DIN*(DIN/2)];
__device__ __half g_owh [DMODEL*DIN];
__device__ __half g_xzH [R0*2*DIN];
__device__ __half g_xs1H[R1*DIN];
__device__ __half g_xs2H[R2*DIN];
__device__ __half g_xcH [RSUM*DIN];
__device__ __half g_dtH [RSUM*DIN];
__device__ __half g_pH  [RSUM*NPROJ];
__device__ __half g_cth [R0*DIN];
__device__ __half g_h1h [R0*(DIN/2)];
__device__ __half g_ach [R0*DIN];

// ---------------- math helpers (MUFU-based) ----------------
__device__ __forceinline__ float ex2a(float x) {
    float y;
    asm("ex2.approx.f32 %0, %1;" : "=f"(y) : "f"(x));
    return y;
}
__device__ __forceinline__ float lg2a(float x) {
    float y;
    asm("lg2.approx.f32 %0, %1;" : "=f"(y) : "f"(x));
    return y;
}
__device__ __forceinline__ float sigmoidf_(float x) {
    return __fdividef(1.0f, 1.0f + ex2a(-x * LOG2E));
}
__device__ __forceinline__ float siluf_(float x) { return x * sigmoidf_(x); }
__device__ __forceinline__ float softplusf_(float x) {
    float u = ex2a(-fabsf(x) * LOG2E);
    return fmaxf(x, 0.0f) + lg2a(1.0f + u) * LN2;
}

// ---------------- convert inputs/weights into fp16 planes ----------------
#define SEG0 (R0*DMODEL)
#define SEG1 (2*DIN*DMODEL)
#define SEG2 (3*NPROJ*DIN)
#define SEG3 (3*DIN*DTRANK)
#define SEG4 ((DIN/2)*DIN)
#define SEG5 (DIN*(DIN/2))
#define SEG6 (DMODEL*DIN)
#define CU0 (SEG0)
#define CU1 (CU0+SEG1)
#define CU2 (CU1+SEG2)
#define CU3 (CU2+SEG3)
#define CU4 (CU3+SEG4)
#define CU5 (CU4+SEG5)
#define CU6 (CU5+SEG6)

__global__ void split_all(const float* __restrict__ x,
                          const float* __restrict__ w1,
                          const float* __restrict__ w2,
                          const float* __restrict__ w3,
                          const float* __restrict__ w4,
                          const float* __restrict__ w5,
                          const float* __restrict__ w6)
{
    long i = ((long)blockIdx.x * blockDim.x + threadIdx.x) * 4;
    if (i >= CU6) return;
    const float* src; __half* dh; long off;
    if      (i < CU0) { src=x;  dh=g_xh;  off=0;   }
    else if (i < CU1) { src=w1; dh=g_wih; off=CU0; }
    else if (i < CU2) { src=w2; dh=g_xph; off=CU1; }
    else if (i < CU3) { src=w3; dh=g_dwh; off=CU2; }
    else if (i < CU4) { src=w4; dh=g_c1h; off=CU3; }
    else if (i < CU5) { src=w5; dh=g_c2h; off=CU4; }
    else              { src=w6; dh=g_owh; off=CU5; }
    long j = i - off;
    float4 v = *(const float4*)(src + j);
    *(__half2*)(dh + j)     = __floats2half2_rn(v.x, v.y);
    *(__half2*)(dh + j + 2) = __floats2half2_rn(v.z, v.w);
}

// ---------------- 5-stage pipelined tensor-core GEMM (pure fp16) ----------------
#define ASTR 40
#define APL (128*ASTR)
#define BPL (64*ASTR)
#define STG (APL + BPL)
#define NSTAGE 5
#define SMEM_BYTES (NSTAGE*STG*2)

__device__ __forceinline__ void ldm_x4(unsigned int* r, const __half* p) {
    unsigned int a = (unsigned int)__cvta_generic_to_shared(p);
    asm volatile("ldmatrix.sync.aligned.m8n8.x4.shared.b16 {%0,%1,%2,%3}, [%4];"
                 : "=r"(r[0]), "=r"(r[1]), "=r"(r[2]), "=r"(r[3]) : "r"(a));
}
__device__ __forceinline__ void mma16816(float* c, const unsigned int* a,
                                         const unsigned int* b) {
    asm volatile(
        "mma.sync.aligned.m16n8k16.row.col.f32.f16.f16.f32 "
        "{%0,%1,%2,%3}, {%4,%5,%6,%7}, {%8,%9}, {%0,%1,%2,%3};"
        : "+f"(c[0]), "+f"(c[1]), "+f"(c[2]), "+f"(c[3])
        : "r"(a[0]), "r"(a[1]), "r"(a[2]), "r"(a[3]), "r"(b[0]), "r"(b[1]));
}
__device__ __forceinline__ void cp16(unsigned int dst, const void* src, bool pred) {
    int sz = pred ? 16 : 0;
    asm volatile("cp.async.cg.shared.global [%0], [%1], 16, %2;\n"
                 :: "r"(dst), "l"(src), "r"(sz));
}

// mode: 0 none | 1 +bias | 2 silu | 3 sigmoid(acc)*e1f*silu(e2h) | 4 +e1f
__global__ void __launch_bounds__(256, 2) gemm_f16(
    const __half* __restrict__ Ahi, int lda,
    const __half* __restrict__ Whi, int ldb, int wstride,
    float* Cf, __half* Chi, int ldc,
    int4 Ms, int4 rowoffs, int N, int K,
    const float* bias, int bstride, int mode,
    const float* e1, int lde1, const __half* e2h, int lde2)
{
    extern __shared__ __align__(16) __half sm[];
    const int z = blockIdx.z;
    const int M      = (z == 0) ? Ms.x      : ((z == 1) ? Ms.y      : Ms.z);
    const int rowoff = (z == 0) ? rowoffs.x : ((z == 1) ? rowoffs.y : rowoffs.z);
    const int m0 = blockIdx.y * 128;
    if (m0 >= M) return;
    const int n0 = blockIdx.x * 64;

    const int tid = threadIdx.x, lane = tid & 31, wid = tid >> 5;
    const int wm = wid & 3, wn = wid >> 2;

    const __half* Ah = Ahi + (size_t)rowoff * lda;
    const __half* Wh = Whi + (size_t)z * wstride;

    const int arow = tid >> 1, acol = (tid & 1) * 16;
    const int brow = tid >> 2, bcol = (tid & 3) * 8;
    const bool bv = (n0 + brow) < N;

    const __half* agh = Ah + (size_t)(m0 + arow) * lda + acol;
    const __half* bgh = Wh + (size_t)(n0 + brow) * ldb + bcol;

    unsigned int sbase = (unsigned int)__cvta_generic_to_shared(sm);
    const int a_dst = arow * ASTR + acol;
    const int b_dst = brow * ASTR + bcol;

    float acc[2][4][4];
    #pragma unroll
    for (int i = 0; i < 2; i++)
        #pragma unroll
        for (int j = 0; j < 4; j++)
            #pragma unroll
            for (int r = 0; r < 4; r++) acc[i][j][r] = 0.0f;

    const int aoff = (wm * 32 + (lane & 15)) * ASTR + (lane >> 4) * 8;
    const int boff = (wn * 32 + ((lane >> 4) << 3) + (lane & 7)) * ASTR
                   + ((lane >> 3) & 1) * 8;

    const int nk = K / 32;

    auto issue = [&](int s) {
        int k0 = s * 32;
        unsigned int st = sbase + (unsigned int)(s % NSTAGE) * (STG * 2);
        cp16(st + (a_dst) * 2,       agh + k0,     true);
        cp16(st + (a_dst + 8) * 2,   agh + k0 + 8, true);
        cp16(st + (APL + b_dst) * 2, bgh + k0,     bv);
    };

    #pragma unroll
    for (int s = 0; s < NSTAGE - 1; s++) {
        if (s < nk) issue(s);
        asm volatile("cp.async.commit_group;\n");
    }

    for (int it = 0; it < nk; it++) {
        asm volatile("cp.async.wait_group %0;\n" :: "n"(NSTAGE - 2));
        __syncthreads();

        int pf = it + NSTAGE - 1;
        if (pf < nk) issue(pf);
        asm volatile("cp.async.commit_group;\n");

        const __half* st = sm + (it % NSTAGE) * STG;
        #pragma unroll
        for (int k16 = 0; k16 < 2; k16++) {
            unsigned int ahif[8];
            unsigned int bhif[8];
            const __half* pa = st + aoff + k16 * 16;
            ldm_x4(&ahif[0], pa);
            ldm_x4(&ahif[4], pa + 16 * ASTR);
            const __half* pb = st + APL + boff + k16 * 16;
            ldm_x4(&bhif[0], pb);
            ldm_x4(&bhif[4], pb + 16 * ASTR);
            #pragma unroll
            for (int mi = 0; mi < 2; mi++) {
                #pragma unroll
                for (int ni = 0; ni < 4; ni++) {
                    mma16816(acc[mi][ni], &ahif[mi * 4], &bhif[ni * 2]);
                }
            }
        }
    }

    // ---- epilogue ----
    #pragma unroll
    for (int mi = 0; mi < 2; mi++) {
        #pragma unroll
        for (int ni = 0; ni < 4; ni++) {
            int mb = m0 + wm * 32 + mi * 16 + (lane >> 2);
            int nb = n0 + wn * 32 + ni * 8 + (lane & 3) * 2;
            #pragma unroll
            for (int r = 0; r < 4; r++) {
                int mloc = mb + ((r >> 1) << 3);
                int n = nb + (r & 1);
                if (n >= N) continue;
                int m = rowoff + mloc;
                float v = acc[mi][ni][r];
                if (mode == 1)      v += bias[z * bstride + n];
                else if (mode == 2) v = siluf_(v);
                else if (mode == 3) v = sigmoidf_(v) * e1[(size_t)m * lde1 + n]
                                  * siluf_(__half2float(e2h[(size_t)m * lde2 + n]));
                else if (mode == 4) v += e1[(size_t)m * lde1 + n];
                size_t o = (size_t)m * ldc + n;
                if (Cf)  Cf[o] = v;
                if (Chi) Chi[o] = __float2half(v);
            }
        }
    }
}

// ---------------- downsample (both scales, one launch; fp16, half2) ----------------
__global__ void down_batched()
{
    int z = blockIdx.y + 1;                 // 1 or 2
    int Tout = TLEN >> z;
    int S = 1 << z;
    float invS = 1.0f / S;
    int total = NB * Tout * (DIN / 2);
    int idx = blockIdx.x * blockDim.x + threadIdx.x;
    if (idx >= total) return;
    int d2 = idx & (DIN/2 - 1);
    int t  = (idx / (DIN/2)) % Tout;
    int b  = idx / (Tout * (DIN/2));
    const __half* p = g_xzH + (size_t)(b * TLEN + t * S) * (2 * DIN) + d2 * 2;
    float sx = 0.f, sy = 0.f;
    #pragma unroll 4
    for (int r = 0; r < S; r++) {
        float2 a = __half22float2(*(const __half2*)(p + (size_t)r * 2 * DIN));
        sx += a.x; sy += a.y;
    }
    __half* dst = (z == 1) ? g_xs1H : g_xs2H;
    *(__half2*)(dst + (size_t)idx * 2) = __floats2half2_rn(sx * invS, sy * invS);
}

// ---------------- depthwise causal conv, temporal-blocked x4, half2 channels ----------------
__global__ void conv_batched(const float* __restrict__ cw,
                             const float* __restrict__ cb)
{
    int z = blockIdx.y;
    int Tl = TLEN >> z;
    int T4 = Tl >> 2;
    int total = NB * T4 * (DIN / 2);
    int idx = blockIdx.x * blockDim.x + threadIdx.x;
    if (idx >= total) return;
    const __half* xin = (z == 0) ? g_xzH : ((z == 1) ? g_xs1H : g_xs2H);
    int ldx = (z == 0) ? 2 * DIN : DIN;
    size_t roff = (z == 0) ? 0 : ((z == 1) ? (size_t)R0 * DIN : (size_t)(R0 + R1) * DIN);

    int d2 = idx & (DIN/2 - 1);
    int t4 = (idx / (DIN/2)) % T4;
    int b  = idx / (T4 * (DIN/2));
    int d  = d2 * 2;
    int t0 = t4 * 4;

    const float4 w0 = *(const float4*)(cw + (size_t)z * DIN * 4 + d * 4);
    const float4 w1 = *(const float4*)(cw + (size_t)z * DIN * 4 + d * 4 + 4);
    const float2 bi = *(const float2*)(cb + (size_t)z * DIN + d);
    float wa[4]; wa[0]=w0.x; wa[1]=w0.y; wa[2]=w0.z; wa[3]=w0.w;
    float wb[4]; wb[0]=w1.x; wb[1]=w1.y; wb[2]=w1.z; wb[3]=w1.w;

    const __half* base = xin + (size_t)(b * Tl) * ldx + d;
    float2 in[7];
    #pragma unroll
    for (int k = 0; k < 7; k++) {
        int tt = t0 + k - 3;
        in[k] = (tt >= 0)
              ? __half22float2(*(const __half2*)(base + (size_t)tt * ldx))
              : make_float2(0.f, 0.f);
    }

    __half* outp = g_xcH + roff + (size_t)(b * Tl + t0) * DIN + d;
    #pragma unroll
    for (int q = 0; q < 4; q++) {
        float ax = bi.x, ay = bi.y;
        #pragma unroll
        for (int k = 0; k < 4; k++) {
            float2 v = in[q + k];
            ax = fmaf(wa[k], v.x, ax);
            ay = fmaf(wb[k], v.y, ay);
        }
        *(__half2*)(outp + (size_t)q * DIN) = __floats2half2_rn(siluf_(ax), siluf_(ay));
    }
}

// ---------------- selective scan: 2 states/thread, 32 channels/block ----------------
// block = 256 thr = 32 channels x 8 state-pairs. grid = (NB*DIN/32, 3).
__global__ void scan_batched(const float* __restrict__ A_log,
                             const float* __restrict__ Dp)
{
    const int z = blockIdx.y;
    const int Tl = TLEN >> z;
    const size_t roff  = (z == 0) ? 0 : ((z == 1) ? (size_t)R0 : (size_t)(R0 + R1));
    const __half* xc   = g_xcH + roff * DIN;
    const float*  proj = g_proj + roff * NPROJ;
    const __half* dt   = g_dtH + roff * DIN;
    float*        y    = g_y   + roff * DIN;
    const float*  Al   = A_log + z * DIN * DSTATE;
    const float*  Dz   = Dp + z * DIN;

    const int sg   = threadIdx.x & 7;        // state-pair index
    const int dloc = threadIdx.x >> 3;       // 0..31
    const int b    = blockIdx.x >> 5;
    const int d0   = (blockIdx.x & 31) * 32;
    const int d    = d0 + dloc;
    const int s0   = sg * 2;

    __shared__ float2 s_ddx[64][32];   // (softplus(dt), dt*xc) per (tt, channel)
    __shared__ float2 s_BC [64][16];   // (B, C) per (tt, state)
    __shared__ float  s_xc [64][32];

    const float Aj0 = -expf(Al[d * 16 + s0])     * LOG2E;
    const float Aj1 = -expf(Al[d * 16 + s0 + 1]) * LOG2E;
    const float Dv  = Dz[d];
    float h0 = 0.0f, h1 = 0.0f;

    for (int t0 = 0; t0 < Tl; t0 += 64) {
        // stage dt/xc: 64 tt x 16 channel-pairs
        for (int i = threadIdx.x; i < 64 * 16; i += 256) {
            int tt = i >> 4;
            int dl = (i & 15) * 2;
            size_t rbase = (size_t)(b * Tl + t0 + tt);
            float2 dtv2 = __half22float2(*(const __half2*)(dt + rbase * DIN + d0 + dl));
            float2 xcv2 = __half22float2(*(const __half2*)(xc + rbase * DIN + d0 + dl));
            float sp0 = softplusf_(dtv2.x), sp1 = softplusf_(dtv2.y);
            s_ddx[tt][dl]   = make_float2(sp0, sp0 * xcv2.x);
            s_ddx[tt][dl+1] = make_float2(sp1, sp1 * xcv2.y);
            s_xc[tt][dl]   = xcv2.x;
            s_xc[tt][dl+1] = xcv2.y;
        }
        // stage B/C: 64 tt x 8 state-pairs
        for (int i = threadIdx.x; i < 64 * 8; i += 256) {
            int tt = i >> 3;
            int sl = (i & 7) * 2;
            size_t rbase = (size_t)(b * Tl + t0 + tt);
            const float* pr = proj + rbase * NPROJ;
            float2 Bv = *(const float2*)(pr + DTRANK + sl);
            float2 Cv = *(const float2*)(pr + DTRANK + DSTATE + sl);
            s_BC[tt][sl]   = make_float2(Bv.x, Cv.x);
            s_BC[tt][sl+1] = make_float2(Bv.y, Cv.y);
        }
        __syncthreads();
        #pragma unroll 4
        for (int tt = 0; tt < 64; tt++) {
            float2 ddx = s_ddx[tt][dloc];
            float4 bc  = *(const float4*)&s_BC[tt][s0];   // (B0,C0,B1,C1)
            float dA0  = fmaxf(ex2a(ddx.x * Aj0), 1e-38f);
            float dA1  = fmaxf(ex2a(ddx.x * Aj1), 1e-38f);
            float dBx0 = fmaxf(ddx.y * bc.x, 1e-38f);
            float dBx1 = fmaxf(ddx.y * bc.z, 1e-38f);
            h0 = fmaf(dA0, h0, dBx0);
            h1 = fmaf(dA1, h1, dBx1);
            float part = fmaf(bc.w, h1, bc.y * h0);
            part += __shfl_xor_sync(0xffffffffu, part, 4);
            part += __shfl_xor_sync(0xffffffffu, part, 2);
            part += __shfl_xor_sync(0xffffffffu, part, 1);
            if (sg == 0)
                y[(size_t)(b * Tl + t0 + tt) * DIN + d] = fmaf(Dv, s_xc[tt][dloc], part);
        }
        __syncthreads();
    }
}

// ---------------- fuse (float4-vectorized, includes scale-weight softmax) ----------------
__global__ void fuse_kernel(const float* __restrict__ sw)
{
    int idx4 = blockIdx.x * blockDim.x + threadIdx.x;   // float4 units
    int d4 = idx4 & (DIN/4 - 1);
    int t  = (idx4 / (DIN/4)) & (TLEN - 1);
    int b  = idx4 / ((DIN/4) * TLEN);
    int d  = d4 * 4;

    float a = sw[0], bb = sw[1], c = sw[2];
    float mx = fmaxf(a, fmaxf(bb, c));
    float ea = ex2a((a - mx) * LOG2E);
    float eb = ex2a((bb - mx) * LOG2E);
    float ec = ex2a((c - mx) * LOG2E);
    float inv = __fdividef(1.0f, ea + eb + ec);
    ea *= inv; eb *= inv; ec *= inv;

    size_t i0 = (size_t)(b * TLEN + t) * DIN + d;
    size_t i1 = (size_t)R0 * DIN + (size_t)(b * (TLEN/2) + (t >> 1)) * DIN + d;
    size_t i2 = (size_t)(R0 + R1) * DIN + (size_t)(b * (TLEN/4) + (t >> 2)) * DIN + d;
    float4 o0 = *(const float4*)(g_y + i0);
    float4 o1 = *(const float4*)(g_y + i1);
    float4 o2 = *(const float4*)(g_y + i2);

    float4 f;
    f.x = ea*o0.x + eb*o1.x + ec*o2.x;
    f.y = ea*o0.y + eb*o1.y + ec*o2.y;
    f.z = ea*o0.z + eb*o1.z + ec*o2.z;
    f.w = ea*o0.w + eb*o1.w + ec*o2.w;
    *(float4*)(g_fused + i0) = f;

    const float th = 1.0f / 3.0f;
    *(__half2*)(g_cth + i0)     = __floats2half2_rn((o0.x+o1.x+o2.x)*th, (o0.y+o1.y+o2.y)*th);
    *(__half2*)(g_cth + i0 + 2) = __floats2half2_rn((o0.z+o1.z+o2.z)*th, (o0.w+o1.w+o2.w)*th);
}

// ---------------- LayerNorm ----------------
__global__ void ln_kernel(const float* __restrict__ gamma,
                          const float* __restrict__ beta,
                          float* __restrict__ out)
{
    int row = blockIdx.x;
    int tid = threadIdx.x;
    const float* r = g_pre + (size_t)row * DMODEL;
    float v1 = r[tid], v2 = r[tid + 256];
    float s  = v1 + v2;
    float q  = v1 * v1 + v2 * v2;
    #pragma unroll
    for (int o = 16; o > 0; o >>= 1) {
        s += __shfl_xor_sync(0xffffffffu, s, o);
        q += __shfl_xor_sync(0xffffffffu, q, o);
    }
    __shared__ float sh[8], sh2[8];
    int wid = tid >> 5, lane = tid & 31;
    if (lane == 0) { sh[wid] = s; sh2[wid] = q; }
    __syncthreads();
    if (tid == 0) {
        float ts = 0.f, tq = 0.f;
        #pragma unroll
        for (int i = 0; i < 8; i++) { ts += sh[i]; tq += sh2[i]; }
        sh[0] = ts; sh2[0] = tq;
    }
    __syncthreads();
    float mu  = sh[0] * (1.0f / DMODEL);
    float var = sh2[0] * (1.0f / DMODEL) - mu * mu;
    float inv = rsqrtf(var + 1e-5f);
    float* o = out + (size_t)row * DMODEL;
    o[tid]       = (v1 - mu) * inv * gamma[tid]       + beta[tid];
    o[tid + 256] = (v2 - mu) * inv * gamma[tid + 256] + beta[tid + 256];
}

// ---------------- driver ----------------
extern "C" void kernel_launch(void* const* d_in, const int* in_sizes, int n_in,
                              void* d_out, int out_size)
{
    const float* x        = (const float*)d_in[0];
    const float* in_proj  = (const float*)d_in[1];
    const float* conv_w   = (const float*)d_in[2];
    const float* conv_b   = (const float*)d_in[3];
    const float* xproj_w  = (const float*)d_in[4];
    const float* dtproj_w = (const float*)d_in[5];
    const float* dtproj_b = (const float*)d_in[6];
    const float* A_log    = (const float*)d_in[7];
    const float* D_p      = (const float*)d_in[8];
    const float* sw       = (const float*)d_in[9];
    const float* cg_w1    = (const float*)d_in[10];
    const float* cg_w2    = (const float*)d_in[11];
    const float* out_w    = (const float*)d_in[12];
    const float* ln_g     = (const float*)d_in[13];
    const float* ln_b     = (const float*)d_in[14];
    float* out            = (float*)d_out;

    static bool attr_set = false;
    if (!attr_set) {
        cudaFuncSetAttribute(gemm_f16, cudaFuncAttributeMaxDynamicSharedMemorySize,
                             SMEM_BYTES);
        attr_set = true;
    }

    float *proj, *fused, *pre;
    __half *xh,*wih,*xph,*dwh,*c1h,*c2h,*owh;
    __half *xzH,*xcH,*dtH,*pH,*cth,*h1h,*ach;
    cudaGetSymbolAddress((void**)&proj, g_proj);
    cudaGetSymbolAddress((void**)&fused,g_fused);
    cudaGetSymbolAddress((void**)&pre,  g_pre);
    cudaGetSymbolAddress((void**)&xh,  g_xh);
    cudaGetSymbolAddress((void**)&wih, g_wih);
    cudaGetSymbolAddress((void**)&xph, g_xph);
    cudaGetSymbolAddress((void**)&dwh, g_dwh);
    cudaGetSymbolAddress((void**)&c1h, g_c1h);
    cudaGetSymbolAddress((void**)&c2h, g_c2h);
    cudaGetSymbolAddress((void**)&owh, g_owh);
    cudaGetSymbolAddress((void**)&xzH, g_xzH);
    cudaGetSymbolAddress((void**)&xcH, g_xcH);
    cudaGetSymbolAddress((void**)&dtH, g_dtH);
    cudaGetSymbolAddress((void**)&pH,  g_pH);
    cudaGetSymbolAddress((void**)&cth, g_cth);
    cudaGetSymbolAddress((void**)&h1h, g_h1h);
    cudaGetSymbolAddress((void**)&ach, g_ach);

    const int4 M1   = make_int4(R0, 0, 0, 0);
    const int4 OFF0 = make_int4(0, 0, 0, 0);
    const int4 M3   = make_int4(R0, R1, R2, 0);
    const int4 OFF3 = make_int4(0, R0, R0 + R1, 0);

    // 0. convert inputs + weights to fp16 planes
    split_all<<<(CU6/4 + 255)/256, 256>>>(x, in_proj, xproj_w, dtproj_w,
                                          cg_w1, cg_w2, out_w);

    // 1. in_proj -> fp16 xz
    gemm_f16<<<dim3(32, 16, 1), 256, SMEM_BYTES>>>(
        xh, DMODEL, wih, DMODEL, 0,
        nullptr, xzH, 2*DIN, M1, OFF0, 2*DIN, DMODEL,
        nullptr, 0, 0, nullptr, 0, nullptr, 0);

    // 2. downsample (both scales, one launch)
    down_batched<<<dim3((R1*DIN/2 + 255)/256, 2), 256>>>();

    // 3. conv (temporal-blocked x4, half2 channels)
    conv_batched<<<dim3((R0*DIN/8 + 255)/256, 3), 256>>>(conv_w, conv_b);

    // 4. xproj (batched): N=96, K=1024
    gemm_f16<<<dim3(2, 16, 3), 256, SMEM_BYTES>>>(
        xcH, DIN, xph, DIN, NPROJ*DIN,
        proj, pH, NPROJ, M3, OFF3, NPROJ, DIN,
        nullptr, 0, 0, nullptr, 0, nullptr, 0);

    // 5. dtproj (batched): N=1024, K=64 (+bias) -> fp16 dt
    gemm_f16<<<dim3(16, 16, 3), 256, SMEM_BYTES>>>(
        pH, NPROJ, dwh, DTRANK, DIN*DTRANK,
        nullptr, dtH, DIN, M3, OFF3, DIN, DTRANK,
        dtproj_b, DIN, 1, nullptr, 0, nullptr, 0);

    // 6. selective scan (2 states/thread, 32 ch/block)
    scan_batched<<<dim3(NB*DIN/32, 3), 256>>>(A_log, D_p);

    // 7. fuse (+softmax), float4-vectorized
    fuse_kernel<<<(R0*DIN/4)/256, 256>>>(sw);

    // 8. context gate
    gemm_f16<<<dim3(8, 16, 1), 256, SMEM_BYTES>>>(
        cth, DIN, c1h, DIN, 0,
        nullptr, h1h, DIN/2, M1, OFF0, DIN/2, DIN,
        nullptr, 0, 2, nullptr, 0, nullptr, 0);
    gemm_f16<<<dim3(16, 16, 1), 256, SMEM_BYTES>>>(
        h1h, DIN/2, c2h, DIN/2, 0,
        nullptr, ach, DIN, M1, OFF0, DIN, DIN/2,
        nullptr, 0, 3, fused, DIN, xzH + DIN, 2*DIN);

    // 9. out_proj + residual
    gemm_f16<<<dim3(8, 16, 1), 256, SMEM_BYTES>>>(
        ach, DIN, owh, DIN, 0,
        pre, nullptr, DMODEL, M1, OFF0, DMODEL, DIN,
        nullptr, 0, 4, x, DMODEL, nullptr, 0);

    // 10. LayerNorm
    ln_kernel<<<R0, 256>>>(ln_g, ln_b, out);
}

// round 16
// speedup vs baseline: 2.0604x; 1.0828x over previous
#include <cuda_runtime.h>
#include <cuda_fp16.h>
#include <stdint.h>
#include <math.h>

// ---------------- problem constants ----------------
#define NB      2
#define TLEN    1024
#define DMODEL  512
#define DIN     1024
#define DTRANK  64
#define DSTATE  16
#define NPROJ   96

#define R0 2048
#define R1 1024
#define R2 512
#define RSUM (R0+R1+R2)

#define LOG2E 1.4426950408889634f
#define LN2   0.6931471805599453f

// ---------------- fp32 scratch ----------------
__device__ float g_proj [RSUM*NPROJ];
__device__ float g_y    [RSUM*DIN];
__device__ float g_fused[R0*DIN];
__device__ float g_pre  [R0*DMODEL];

// ---------------- fp16 planes ----------------
__device__ __half g_xh  [R0*DMODEL];
__device__ __half g_wih [2*DIN*DMODEL];
__device__ __half g_xph [3*NPROJ*DIN];
__device__ __half g_dwh [3*DIN*DTRANK];
__device__ __half g_c1h [(DIN/2)*DIN];
__device__ __half g_c2h [DIN*(DIN/2)];
__device__ __half g_owh [DMODEL*DIN];
__device__ __half g_xzH [R0*2*DIN];
__device__ __half g_xs1H[R1*DIN];
__device__ __half g_xs2H[R2*DIN];
__device__ __half g_xcH [RSUM*DIN];
__device__ __half g_dtH [RSUM*DIN];
__device__ __half g_pH  [RSUM*NPROJ];
__device__ __half g_cth [R0*DIN];
__device__ __half g_h1h [R0*(DIN/2)];
__device__ __half g_ach [R0*DIN];

// ---------------- math helpers (MUFU-based) ----------------
__device__ __forceinline__ float ex2a(float x) {
    float y;
    asm("ex2.approx.f32 %0, %1;" : "=f"(y) : "f"(x));
    return y;
}
__device__ __forceinline__ float lg2a(float x) {
    float y;
    asm("lg2.approx.f32 %0, %1;" : "=f"(y) : "f"(x));
    return y;
}
__device__ __forceinline__ float sigmoidf_(float x) {
    return __fdividef(1.0f, 1.0f + ex2a(-x * LOG2E));
}
__device__ __forceinline__ float siluf_(float x) { return x * sigmoidf_(x); }
__device__ __forceinline__ float softplusf_(float x) {
    float u = ex2a(-fabsf(x) * LOG2E);
    return fmaxf(x, 0.0f) + lg2a(1.0f + u) * LN2;
}

// ---------------- convert inputs/weights into fp16 planes ----------------
#define SEG0 (R0*DMODEL)
#define SEG1 (2*DIN*DMODEL)
#define SEG2 (3*NPROJ*DIN)
#define SEG3 (3*DIN*DTRANK)
#define SEG4 ((DIN/2)*DIN)
#define SEG5 (DIN*(DIN/2))
#define SEG6 (DMODEL*DIN)
#define CU0 (SEG0)
#define CU1 (CU0+SEG1)
#define CU2 (CU1+SEG2)
#define CU3 (CU2+SEG3)
#define CU4 (CU3+SEG4)
#define CU5 (CU4+SEG5)
#define CU6 (CU5+SEG6)

__global__ void split_all(const float* __restrict__ x,
                          const float* __restrict__ w1,
                          const float* __restrict__ w2,
                          const float* __restrict__ w3,
                          const float* __restrict__ w4,
                          const float* __restrict__ w5,
                          const float* __restrict__ w6)
{
    long i = ((long)blockIdx.x * blockDim.x + threadIdx.x) * 4;
    if (i >= CU6) return;
    const float* src; __half* dh; long off;
    if      (i < CU0) { src=x;  dh=g_xh;  off=0;   }
    else if (i < CU1) { src=w1; dh=g_wih; off=CU0; }
    else if (i < CU2) { src=w2; dh=g_xph; off=CU1; }
    else if (i < CU3) { src=w3; dh=g_dwh; off=CU2; }
    else if (i < CU4) { src=w4; dh=g_c1h; off=CU3; }
    else if (i < CU5) { src=w5; dh=g_c2h; off=CU4; }
    else              { src=w6; dh=g_owh; off=CU5; }
    long j = i - off;
    float4 v = *(const float4*)(src + j);
    *(__half2*)(dh + j)     = __floats2half2_rn(v.x, v.y);
    *(__half2*)(dh + j + 2) = __floats2half2_rn(v.z, v.w);
}

// ---------------- 5-stage pipelined tensor-core GEMM (pure fp16) ----------------
#define ASTR 40
#define APL (128*ASTR)
#define BPL (64*ASTR)
#define STG (APL + BPL)
#define NSTAGE 5
#define SMEM_BYTES (NSTAGE*STG*2)

__device__ __forceinline__ void ldm_x4(unsigned int* r, const __half* p) {
    unsigned int a = (unsigned int)__cvta_generic_to_shared(p);
    asm volatile("ldmatrix.sync.aligned.m8n8.x4.shared.b16 {%0,%1,%2,%3}, [%4];"
                 : "=r"(r[0]), "=r"(r[1]), "=r"(r[2]), "=r"(r[3]) : "r"(a));
}
__device__ __forceinline__ void mma16816(float* c, const unsigned int* a,
                                         const unsigned int* b) {
    asm volatile(
        "mma.sync.aligned.m16n8k16.row.col.f32.f16.f16.f32 "
        "{%0,%1,%2,%3}, {%4,%5,%6,%7}, {%8,%9}, {%0,%1,%2,%3};"
        : "+f"(c[0]), "+f"(c[1]), "+f"(c[2]), "+f"(c[3])
        : "r"(a[0]), "r"(a[1]), "r"(a[2]), "r"(a[3]), "r"(b[0]), "r"(b[1]));
}
__device__ __forceinline__ void cp16(unsigned int dst, const void* src, bool pred) {
    int sz = pred ? 16 : 0;
    asm volatile("cp.async.cg.shared.global [%0], [%1], 16, %2;\n"
                 :: "r"(dst), "l"(src), "r"(sz));
}

// mode: 0 none | 1 +bias | 2 silu | 3 sigmoid(acc)*e1f*silu(e2h) | 4 +e1f
__global__ void __launch_bounds__(256, 2) gemm_f16(
    const __half* __restrict__ Ahi, int lda,
    const __half* __restrict__ Whi, int ldb, int wstride,
    float* Cf, __half* Chi, int ldc,
    int4 Ms, int4 rowoffs, int N, int K,
    const float* bias, int bstride, int mode,
    const float* e1, int lde1, const __half* e2h, int lde2)
{
    extern __shared__ __align__(16) __half sm[];
    const int z = blockIdx.z;
    const int M      = (z == 0) ? Ms.x      : ((z == 1) ? Ms.y      : Ms.z);
    const int rowoff = (z == 0) ? rowoffs.x : ((z == 1) ? rowoffs.y : rowoffs.z);
    const int m0 = blockIdx.y * 128;
    if (m0 >= M) return;
    const int n0 = blockIdx.x * 64;

    const int tid = threadIdx.x, lane = tid & 31, wid = tid >> 5;
    const int wm = wid & 3, wn = wid >> 2;

    const __half* Ah = Ahi + (size_t)rowoff * lda;
    const __half* Wh = Whi + (size_t)z * wstride;

    const int arow = tid >> 1, acol = (tid & 1) * 16;
    const int brow = tid >> 2, bcol = (tid & 3) * 8;
    const bool bv = (n0 + brow) < N;

    const __half* agh = Ah + (size_t)(m0 + arow) * lda + acol;
    const __half* bgh = Wh + (size_t)(n0 + brow) * ldb + bcol;

    unsigned int sbase = (unsigned int)__cvta_generic_to_shared(sm);
    const int a_dst = arow * ASTR + acol;
    const int b_dst = brow * ASTR + bcol;

    float acc[2][4][4];
    #pragma unroll
    for (int i = 0; i < 2; i++)
        #pragma unroll
        for (int j = 0; j < 4; j++)
            #pragma unroll
            for (int r = 0; r < 4; r++) acc[i][j][r] = 0.0f;

    const int aoff = (wm * 32 + (lane & 15)) * ASTR + (lane >> 4) * 8;
    const int boff = (wn * 32 + ((lane >> 4) << 3) + (lane & 7)) * ASTR
                   + ((lane >> 3) & 1) * 8;

    const int nk = K / 32;

    auto issue = [&](int s) {
        int k0 = s * 32;
        unsigned int st = sbase + (unsigned int)(s % NSTAGE) * (STG * 2);
        cp16(st + (a_dst) * 2,       agh + k0,     true);
        cp16(st + (a_dst + 8) * 2,   agh + k0 + 8, true);
        cp16(st + (APL + b_dst) * 2, bgh + k0,     bv);
    };

    #pragma unroll
    for (int s = 0; s < NSTAGE - 1; s++) {
        if (s < nk) issue(s);
        asm volatile("cp.async.commit_group;\n");
    }

    for (int it = 0; it < nk; it++) {
        asm volatile("cp.async.wait_group %0;\n" :: "n"(NSTAGE - 2));
        __syncthreads();

        int pf = it + NSTAGE - 1;
        if (pf < nk) issue(pf);
        asm volatile("cp.async.commit_group;\n");

        const __half* st = sm + (it % NSTAGE) * STG;
        #pragma unroll
        for (int k16 = 0; k16 < 2; k16++) {
            unsigned int ahif[8];
            unsigned int bhif[8];
            const __half* pa = st + aoff + k16 * 16;
            ldm_x4(&ahif[0], pa);
            ldm_x4(&ahif[4], pa + 16 * ASTR);
            const __half* pb = st + APL + boff + k16 * 16;
            ldm_x4(&bhif[0], pb);
            ldm_x4(&bhif[4], pb + 16 * ASTR);
            #pragma unroll
            for (int mi = 0; mi < 2; mi++) {
                #pragma unroll
                for (int ni = 0; ni < 4; ni++) {
                    mma16816(acc[mi][ni], &ahif[mi * 4], &bhif[ni * 2]);
                }
            }
        }
    }

    // ---- epilogue (vectorized: acc[..][r2*2]/[r2*2+1] are adjacent n) ----
    #pragma unroll
    for (int mi = 0; mi < 2; mi++) {
        #pragma unroll
        for (int ni = 0; ni < 4; ni++) {
            int mb = m0 + wm * 32 + mi * 16 + (lane >> 2);
            int n  = n0 + wn * 32 + ni * 8 + (lane & 3) * 2;   // even
            if (n >= N) continue;
            #pragma unroll
            for (int r2 = 0; r2 < 2; r2++) {                   // row group
                int m = rowoff + mb + r2 * 8;
                float v0 = acc[mi][ni][r2 * 2];
                float v1 = acc[mi][ni][r2 * 2 + 1];
                if (mode == 1) {
                    float2 bv2 = *(const float2*)(bias + z * bstride + n);
                    v0 += bv2.x; v1 += bv2.y;
                } else if (mode == 2) {
                    v0 = siluf_(v0); v1 = siluf_(v1);
                } else if (mode == 3) {
                    float2 f1 = *(const float2*)(e1 + (size_t)m * lde1 + n);
                    float2 f2 = __half22float2(*(const __half2*)(e2h + (size_t)m * lde2 + n));
                    v0 = sigmoidf_(v0) * f1.x * siluf_(f2.x);
                    v1 = sigmoidf_(v1) * f1.y * siluf_(f2.y);
                } else if (mode == 4) {
                    float2 f1 = *(const float2*)(e1 + (size_t)m * lde1 + n);
                    v0 += f1.x; v1 += f1.y;
                }
                size_t o = (size_t)m * ldc + n;
                if (Cf)  *(float2*)(Cf + o) = make_float2(v0, v1);
                if (Chi) *(__half2*)(Chi + o) = __floats2half2_rn(v0, v1);
            }
        }
    }
}

// ---------------- downsample (both scales, one launch; fp16, half2) ----------------
__global__ void down_batched()
{
    int z = blockIdx.y + 1;                 // 1 or 2
    int Tout = TLEN >> z;
    int S = 1 << z;
    float invS = 1.0f / S;
    int total = NB * Tout * (DIN / 2);
    int idx = blockIdx.x * blockDim.x + threadIdx.x;
    if (idx >= total) return;
    int d2 = idx & (DIN/2 - 1);
    int t  = (idx / (DIN/2)) % Tout;
    int b  = idx / (Tout * (DIN/2));
    const __half* p = g_xzH + (size_t)(b * TLEN + t * S) * (2 * DIN) + d2 * 2;
    float sx = 0.f, sy = 0.f;
    #pragma unroll 4
    for (int r = 0; r < S; r++) {
        float2 a = __half22float2(*(const __half2*)(p + (size_t)r * 2 * DIN));
        sx += a.x; sy += a.y;
    }
    __half* dst = (z == 1) ? g_xs1H : g_xs2H;
    *(__half2*)(dst + (size_t)idx * 2) = __floats2half2_rn(sx * invS, sy * invS);
}

// ---------------- depthwise causal conv, temporal-blocked x4, half2 channels ----------------
__global__ void conv_batched(const float* __restrict__ cw,
                             const float* __restrict__ cb)
{
    int z = blockIdx.y;
    int Tl = TLEN >> z;
    int T4 = Tl >> 2;
    int total = NB * T4 * (DIN / 2);
    int idx = blockIdx.x * blockDim.x + threadIdx.x;
    if (idx >= total) return;
    const __half* xin = (z == 0) ? g_xzH : ((z == 1) ? g_xs1H : g_xs2H);
    int ldx = (z == 0) ? 2 * DIN : DIN;
    size_t roff = (z == 0) ? 0 : ((z == 1) ? (size_t)R0 * DIN : (size_t)(R0 + R1) * DIN);

    int d2 = idx & (DIN/2 - 1);
    int t4 = (idx / (DIN/2)) % T4;
    int b  = idx / (T4 * (DIN/2));
    int d  = d2 * 2;
    int t0 = t4 * 4;

    const float4 w0 = *(const float4*)(cw + (size_t)z * DIN * 4 + d * 4);
    const float4 w1 = *(const float4*)(cw + (size_t)z * DIN * 4 + d * 4 + 4);
    const float2 bi = *(const float2*)(cb + (size_t)z * DIN + d);
    float wa[4]; wa[0]=w0.x; wa[1]=w0.y; wa[2]=w0.z; wa[3]=w0.w;
    float wb[4]; wb[0]=w1.x; wb[1]=w1.y; wb[2]=w1.z; wb[3]=w1.w;

    const __half* base = xin + (size_t)(b * Tl) * ldx + d;
    float2 in[7];
    #pragma unroll
    for (int k = 0; k < 7; k++) {
        int tt = t0 + k - 3;
        in[k] = (tt >= 0)
              ? __half22float2(*(const __half2*)(base + (size_t)tt * ldx))
              : make_float2(0.f, 0.f);
    }

    __half* outp = g_xcH + roff + (size_t)(b * Tl + t0) * DIN + d;
    #pragma unroll
    for (int q = 0; q < 4; q++) {
        float ax = bi.x, ay = bi.y;
        #pragma unroll
        for (int k = 0; k < 4; k++) {
            float2 v = in[q + k];
            ax = fmaf(wa[k], v.x, ax);
            ay = fmaf(wb[k], v.y, ay);
        }
        *(__half2*)(outp + (size_t)q * DIN) = __floats2half2_rn(siluf_(ax), siluf_(ay));
    }
}

// ---------------- selective scan: 2 states/thread, 32 channels/block ----------------
__global__ void scan_batched(const float* __restrict__ A_log,
                             const float* __restrict__ Dp)
{
    const int z = blockIdx.y;
    const int Tl = TLEN >> z;
    const size_t roff  = (z == 0) ? 0 : ((z == 1) ? (size_t)R0 : (size_t)(R0 + R1));
    const __half* xc   = g_xcH + roff * DIN;
    const float*  proj = g_proj + roff * NPROJ;
    const __half* dt   = g_dtH + roff * DIN;
    float*        y    = g_y   + roff * DIN;
    const float*  Al   = A_log + z * DIN * DSTATE;
    const float*  Dz   = Dp + z * DIN;

    const int sg   = threadIdx.x & 7;
    const int dloc = threadIdx.x >> 3;
    const int b    = blockIdx.x >> 5;
    const int d0   = (blockIdx.x & 31) * 32;
    const int d    = d0 + dloc;
    const int s0   = sg * 2;

    __shared__ float2 s_ddx[64][32];
    __shared__ float2 s_BC [64][16];
    __shared__ float  s_xc [64][32];

    const float Aj0 = -expf(Al[d * 16 + s0])     * LOG2E;
    const float Aj1 = -expf(Al[d * 16 + s0 + 1]) * LOG2E;
    const float Dv  = Dz[d];
    float h0 = 0.0f, h1 = 0.0f;

    for (int t0 = 0; t0 < Tl; t0 += 64) {
        for (int i = threadIdx.x; i < 64 * 16; i += 256) {
            int tt = i >> 4;
            int dl = (i & 15) * 2;
            size_t rbase = (size_t)(b * Tl + t0 + tt);
            float2 dtv2 = __half22float2(*(const __half2*)(dt + rbase * DIN + d0 + dl));
            float2 xcv2 = __half22float2(*(const __half2*)(xc + rbase * DIN + d0 + dl));
            float sp0 = softplusf_(dtv2.x), sp1 = softplusf_(dtv2.y);
            s_ddx[tt][dl]   = make_float2(sp0, sp0 * xcv2.x);
            s_ddx[tt][dl+1] = make_float2(sp1, sp1 * xcv2.y);
            s_xc[tt][dl]   = xcv2.x;
            s_xc[tt][dl+1] = xcv2.y;
        }
        for (int i = threadIdx.x; i < 64 * 8; i += 256) {
            int tt = i >> 3;
            int sl = (i & 7) * 2;
            size_t rbase = (size_t)(b * Tl + t0 + tt);
            const float* pr = proj + rbase * NPROJ;
            float2 Bv = *(const float2*)(pr + DTRANK + sl);
            float2 Cv = *(const float2*)(pr + DTRANK + DSTATE + sl);
            s_BC[tt][sl]   = make_float2(Bv.x, Cv.x);
            s_BC[tt][sl+1] = make_float2(Bv.y, Cv.y);
        }
        __syncthreads();
        #pragma unroll 4
        for (int tt = 0; tt < 64; tt++) {
            float2 ddx = s_ddx[tt][dloc];
            float4 bc  = *(const float4*)&s_BC[tt][s0];
            float dA0  = fmaxf(ex2a(ddx.x * Aj0), 1e-38f);
            float dA1  = fmaxf(ex2a(ddx.x * Aj1), 1e-38f);
            float dBx0 = fmaxf(ddx.y * bc.x, 1e-38f);
            float dBx1 = fmaxf(ddx.y * bc.z, 1e-38f);
            h0 = fmaf(dA0, h0, dBx0);
            h1 = fmaf(dA1, h1, dBx1);
            float part = fmaf(bc.w, h1, bc.y * h0);
            part += __shfl_xor_sync(0xffffffffu, part, 4);
            part += __shfl_xor_sync(0xffffffffu, part, 2);
            part += __shfl_xor_sync(0xffffffffu, part, 1);
            if (sg == 0)
                y[(size_t)(b * Tl + t0 + tt) * DIN + d] = fmaf(Dv, s_xc[tt][dloc], part);
        }
        __syncthreads();
    }
}

// ---------------- fuse (float4-vectorized, includes scale-weight softmax) ----------------
__global__ void fuse_kernel(const float* __restrict__ sw)
{
    int idx4 = blockIdx.x * blockDim.x + threadIdx.x;
    int d4 = idx4 & (DIN/4 - 1);
    int t  = (idx4 / (DIN/4)) & (TLEN - 1);
    int b  = idx4 / ((DIN/4) * TLEN);
    int d  = d4 * 4;

    float a = sw[0], bb = sw[1], c = sw[2];
    float mx = fmaxf(a, fmaxf(bb, c));
    float ea = ex2a((a - mx) * LOG2E);
    float eb = ex2a((bb - mx) * LOG2E);
    float ec = ex2a((c - mx) * LOG2E);
    float inv = __fdividef(1.0f, ea + eb + ec);
    ea *= inv; eb *= inv; ec *= inv;

    size_t i0 = (size_t)(b * TLEN + t) * DIN + d;
    size_t i1 = (size_t)R0 * DIN + (size_t)(b * (TLEN/2) + (t >> 1)) * DIN + d;
    size_t i2 = (size_t)(R0 + R1) * DIN + (size_t)(b * (TLEN/4) + (t >> 2)) * DIN + d;
    float4 o0 = *(const float4*)(g_y + i0);
    float4 o1 = *(const float4*)(g_y + i1);
    float4 o2 = *(const float4*)(g_y + i2);

    float4 f;
    f.x = ea*o0.x + eb*o1.x + ec*o2.x;
    f.y = ea*o0.y + eb*o1.y + ec*o2.y;
    f.z = ea*o0.z + eb*o1.z + ec*o2.z;
    f.w = ea*o0.w + eb*o1.w + ec*o2.w;
    *(float4*)(g_fused + i0) = f;

    const float th = 1.0f / 3.0f;
    *(__half2*)(g_cth + i0)     = __floats2half2_rn((o0.x+o1.x+o2.x)*th, (o0.y+o1.y+o2.y)*th);
    *(__half2*)(g_cth + i0 + 2) = __floats2half2_rn((o0.z+o1.z+o2.z)*th, (o0.w+o1.w+o2.w)*th);
}

// ---------------- LayerNorm ----------------
__global__ void ln_kernel(const float* __restrict__ gamma,
                          const float* __restrict__ beta,
                          float* __restrict__ out)
{
    int row = blockIdx.x;
    int tid = threadIdx.x;
    const float* r = g_pre + (size_t)row * DMODEL;
    float v1 = r[tid], v2 = r[tid + 256];
    float s  = v1 + v2;
    float q  = v1 * v1 + v2 * v2;
    #pragma unroll
    for (int o = 16; o > 0; o >>= 1) {
        s += __shfl_xor_sync(0xffffffffu, s, o);
        q += __shfl_xor_sync(0xffffffffu, q, o);
    }
    __shared__ float sh[8], sh2[8];
    int wid = tid >> 5, lane = tid & 31;
    if (lane == 0) { sh[wid] = s; sh2[wid] = q; }
    __syncthreads();
    if (tid == 0) {
        float ts = 0.f, tq = 0.f;
        #pragma unroll
        for (int i = 0; i < 8; i++) { ts += sh[i]; tq += sh2[i]; }
        sh[0] = ts; sh2[0] = tq;
    }
    __syncthreads();
    float mu  = sh[0] * (1.0f / DMODEL);
    float var = sh2[0] * (1.0f / DMODEL) - mu * mu;
    float inv = rsqrtf(var + 1e-5f);
    float* o = out + (size_t)row * DMODEL;
    o[tid]       = (v1 - mu) * inv * gamma[tid]       + beta[tid];
    o[tid + 256] = (v2 - mu) * inv * gamma[tid + 256] + beta[tid + 256];
}

// ---------------- driver ----------------
extern "C" void kernel_launch(void* const* d_in, const int* in_sizes, int n_in,
                              void* d_out, int out_size)
{
    const float* x        = (const float*)d_in[0];
    const float* in_proj  = (const float*)d_in[1];
    const float* conv_w   = (const float*)d_in[2];
    const float* conv_b   = (const float*)d_in[3];
    const float* xproj_w  = (const float*)d_in[4];
    const float* dtproj_w = (const float*)d_in[5];
    const float* dtproj_b = (const float*)d_in[6];
    const float* A_log    = (const float*)d_in[7];
    const float* D_p      = (const float*)d_in[8];
    const float* sw       = (const float*)d_in[9];
    const float* cg_w1    = (const float*)d_in[10];
    const float* cg_w2    = (const float*)d_in[11];
    const float* out_w    = (const float*)d_in[12];
    const float* ln_g     = (const float*)d_in[13];
    const float* ln_b     = (const float*)d_in[14];
    float* out            = (float*)d_out;

    static bool attr_set = false;
    if (!attr_set) {
        cudaFuncSetAttribute(gemm_f16, cudaFuncAttributeMaxDynamicSharedMemorySize,
                             SMEM_BYTES);
        attr_set = true;
    }

    float *proj, *fused, *pre;
    __half *xh,*wih,*xph,*dwh,*c1h,*c2h,*owh;
    __half *xzH,*xcH,*dtH,*pH,*cth,*h1h,*ach;
    cudaGetSymbolAddress((void**)&proj, g_proj);
    cudaGetSymbolAddress((void**)&fused,g_fused);
    cudaGetSymbolAddress((void**)&pre,  g_pre);
    cudaGetSymbolAddress((void**)&xh,  g_xh);
    cudaGetSymbolAddress((void**)&wih, g_wih);
    cudaGetSymbolAddress((void**)&xph, g_xph);
    cudaGetSymbolAddress((void**)&dwh, g_dwh);
    cudaGetSymbolAddress((void**)&c1h, g_c1h);
    cudaGetSymbolAddress((void**)&c2h, g_c2h);
    cudaGetSymbolAddress((void**)&owh, g_owh);
    cudaGetSymbolAddress((void**)&xzH, g_xzH);
    cudaGetSymbolAddress((void**)&xcH, g_xcH);
    cudaGetSymbolAddress((void**)&dtH, g_dtH);
    cudaGetSymbolAddress((void**)&pH,  g_pH);
    cudaGetSymbolAddress((void**)&cth, g_cth);
    cudaGetSymbolAddress((void**)&h1h, g_h1h);
    cudaGetSymbolAddress((void**)&ach, g_ach);

    const int4 M1   = make_int4(R0, 0, 0, 0);
    const int4 OFF0 = make_int4(0, 0, 0, 0);
    const int4 M3   = make_int4(R0, R1, R2, 0);
    const int4 OFF3 = make_int4(0, R0, R0 + R1, 0);

    // 0. convert inputs + weights to fp16 planes
    split_all<<<(CU6/4 + 255)/256, 256>>>(x, in_proj, xproj_w, dtproj_w,
                                          cg_w1, cg_w2, out_w);

    // 1. in_proj -> fp16 xz
    gemm_f16<<<dim3(32, 16, 1), 256, SMEM_BYTES>>>(
        xh, DMODEL, wih, DMODEL, 0,
        nullptr, xzH, 2*DIN, M1, OFF0, 2*DIN, DMODEL,
        nullptr, 0, 0, nullptr, 0, nullptr, 0);

    // 2. downsample (both scales, one launch)
    down_batched<<<dim3((R1*DIN/2 + 255)/256, 2), 256>>>();

    // 3. conv (temporal-blocked x4, half2 channels)
    conv_batched<<<dim3((R0*DIN/8 + 255)/256, 3), 256>>>(conv_w, conv_b);

    // 4. xproj (batched): N=96, K=1024
    gemm_f16<<<dim3(2, 16, 3), 256, SMEM_BYTES>>>(
        xcH, DIN, xph, DIN, NPROJ*DIN,
        proj, pH, NPROJ, M3, OFF3, NPROJ, DIN,
        nullptr, 0, 0, nullptr, 0, nullptr, 0);

    // 5. dtproj (batched): N=1024, K=64 (+bias) -> fp16 dt
    gemm_f16<<<dim3(16, 16, 3), 256, SMEM_BYTES>>>(
        pH, NPROJ, dwh, DTRANK, DIN*DTRANK,
        nullptr, dtH, DIN, M3, OFF3, DIN, DTRANK,
        dtproj_b, DIN, 1, nullptr, 0, nullptr, 0);

    // 6. selective scan (2 states/thread, 32 ch/block)
    scan_batched<<<dim3(NB*DIN/32, 3), 256>>>(A_log, D_p);

    // 7. fuse (+softmax), float4-vectorized
    fuse_kernel<<<(R0*DIN/4)/256, 256>>>(sw);

    // 8. context gate
    gemm_f16<<<dim3(8, 16, 1), 256, SMEM_BYTES>>>(
        cth, DIN, c1h, DIN, 0,
        nullptr, h1h, DIN/2, M1, OFF0, DIN/2, DIN,
        nullptr, 0, 2, nullptr, 0, nullptr, 0);
    gemm_f16<<<dim3(16, 16, 1), 256, SMEM_BYTES>>>(
        h1h, DIN/2, c2h, DIN/2, 0,
        nullptr, ach, DIN, M1, OFF0, DIN, DIN/2,
        nullptr, 0, 3, fused, DIN, xzH + DIN, 2*DIN);

    // 9. out_proj + residual
    gemm_f16<<<dim3(8, 16, 1), 256, SMEM_BYTES>>>(
        ach, DIN, owh, DIN, 0,
        pre, nullptr, DMODEL, M1, OFF0, DMODEL, DIN,
        nullptr, 0, 4, x, DMODEL, nullptr, 0);

    // 10. LayerNorm
    ln_kernel<<<R0, 256>>>(ln_g, ln_b, out);
}

// round 17
// speedup vs baseline: 2.1153x; 1.0266x over previous
#include <cuda_runtime.h>
#include <cuda_fp16.h>
#include <stdint.h>
#include <math.h>

// ---------------- problem constants ----------------
#define NB      2
#define TLEN    1024
#define DMODEL  512
#define DIN     1024
#define DTRANK  64
#define DSTATE  16
#define NPROJ   96

#define R0 2048
#define R1 1024
#define R2 512
#define RSUM (R0+R1+R2)

#define LOG2E 1.4426950408889634f
#define LN2   0.6931471805599453f

// ---------------- fp32 scratch ----------------
__device__ float g_proj [RSUM*NPROJ];
__device__ float g_y    [RSUM*DIN];
__device__ float g_fused[R0*DIN];
__device__ float g_pre  [R0*DMODEL];

// ---------------- fp16 planes ----------------
__device__ __half g_xh  [R0*DMODEL];
__device__ __half g_wih [2*DIN*DMODEL];
__device__ __half g_xph [3*NPROJ*DIN];
__device__ __half g_dwh [3*DIN*DTRANK];
__device__ __half g_c1h [(DIN/2)*DIN];
__device__ __half g_c2h [DIN*(DIN/2)];
__device__ __half g_owh [DMODEL*DIN];
__device__ __half g_xzH [R0*2*DIN];
__device__ __half g_xs1H[R1*DIN];
__device__ __half g_xs2H[R2*DIN];
__device__ __half g_xcH [RSUM*DIN];
__device__ __half g_dtH [RSUM*DIN];
__device__ __half g_pH  [RSUM*NPROJ];
__device__ __half g_cth [R0*DIN];
__device__ __half g_h1h [R0*(DIN/2)];
__device__ __half g_ach [R0*DIN];

// ---------------- math helpers (MUFU-based) ----------------
__device__ __forceinline__ float ex2a(float x) {
    float y;
    asm("ex2.approx.f32 %0, %1;" : "=f"(y) : "f"(x));
    return y;
}
__device__ __forceinline__ float lg2a(float x) {
    float y;
    asm("lg2.approx.f32 %0, %1;" : "=f"(y) : "f"(x));
    return y;
}
__device__ __forceinline__ float sigmoidf_(float x) {
    return __fdividef(1.0f, 1.0f + ex2a(-x * LOG2E));
}
__device__ __forceinline__ float siluf_(float x) { return x * sigmoidf_(x); }
__device__ __forceinline__ float softplusf_(float x) {
    float u = ex2a(-fabsf(x) * LOG2E);
    return fmaxf(x, 0.0f) + lg2a(1.0f + u) * LN2;
}

// ---------------- convert inputs/weights into fp16 planes ----------------
#define SEG0 (R0*DMODEL)
#define SEG1 (2*DIN*DMODEL)
#define SEG2 (3*NPROJ*DIN)
#define SEG3 (3*DIN*DTRANK)
#define SEG4 ((DIN/2)*DIN)
#define SEG5 (DIN*(DIN/2))
#define SEG6 (DMODEL*DIN)
#define CU0 (SEG0)
#define CU1 (CU0+SEG1)
#define CU2 (CU1+SEG2)
#define CU3 (CU2+SEG3)
#define CU4 (CU3+SEG4)
#define CU5 (CU4+SEG5)
#define CU6 (CU5+SEG6)

__global__ void split_all(const float* __restrict__ x,
                          const float* __restrict__ w1,
                          const float* __restrict__ w2,
                          const float* __restrict__ w3,
                          const float* __restrict__ w4,
                          const float* __restrict__ w5,
                          const float* __restrict__ w6)
{
    long i = ((long)blockIdx.x * blockDim.x + threadIdx.x) * 4;
    if (i >= CU6) return;
    const float* src; __half* dh; long off;
    if      (i < CU0) { src=x;  dh=g_xh;  off=0;   }
    else if (i < CU1) { src=w1; dh=g_wih; off=CU0; }
    else if (i < CU2) { src=w2; dh=g_xph; off=CU1; }
    else if (i < CU3) { src=w3; dh=g_dwh; off=CU2; }
    else if (i < CU4) { src=w4; dh=g_c1h; off=CU3; }
    else if (i < CU5) { src=w5; dh=g_c2h; off=CU4; }
    else              { src=w6; dh=g_owh; off=CU5; }
    long j = i - off;
    float4 v = *(const float4*)(src + j);
    *(__half2*)(dh + j)     = __floats2half2_rn(v.x, v.y);
    *(__half2*)(dh + j + 2) = __floats2half2_rn(v.z, v.w);
}

// ---------------- shared GEMM helpers ----------------
#define ASTR 40
#define NSTAGE 5

__device__ __forceinline__ void ldm_x4(unsigned int* r, const __half* p) {
    unsigned int a = (unsigned int)__cvta_generic_to_shared(p);
    asm volatile("ldmatrix.sync.aligned.m8n8.x4.shared.b16 {%0,%1,%2,%3}, [%4];"
                 : "=r"(r[0]), "=r"(r[1]), "=r"(r[2]), "=r"(r[3]) : "r"(a));
}
__device__ __forceinline__ void mma16816(float* c, const unsigned int* a,
                                         const unsigned int* b) {
    asm volatile(
        "mma.sync.aligned.m16n8k16.row.col.f32.f16.f16.f32 "
        "{%0,%1,%2,%3}, {%4,%5,%6,%7}, {%8,%9}, {%0,%1,%2,%3};"
        : "+f"(c[0]), "+f"(c[1]), "+f"(c[2]), "+f"(c[3])
        : "r"(a[0]), "r"(a[1]), "r"(a[2]), "r"(a[3]), "r"(b[0]), "r"(b[1]));
}
__device__ __forceinline__ void cp16(unsigned int dst, const void* src, bool pred) {
    int sz = pred ? 16 : 0;
    asm volatile("cp.async.cg.shared.global [%0], [%1], 16, %2;\n"
                 :: "r"(dst), "l"(src), "r"(sz));
}

// epilogue helper (shared by both tiles)
__device__ __forceinline__ void epi_pair(
    float v0, float v1, int m, int n, int z,
    float* Cf, __half* Chi, int ldc,
    const float* bias, int bstride, int mode,
    const float* e1, int lde1, const __half* e2h, int lde2)
{
    if (mode == 1) {
        float2 bv2 = *(const float2*)(bias + z * bstride + n);
        v0 += bv2.x; v1 += bv2.y;
    } else if (mode == 2) {
        v0 = siluf_(v0); v1 = siluf_(v1);
    } else if (mode == 3) {
        float2 f1 = *(const float2*)(e1 + (size_t)m * lde1 + n);
        float2 f2 = __half22float2(*(const __half2*)(e2h + (size_t)m * lde2 + n));
        v0 = sigmoidf_(v0) * f1.x * siluf_(f2.x);
        v1 = sigmoidf_(v1) * f1.y * siluf_(f2.y);
    } else if (mode == 4) {
        float2 f1 = *(const float2*)(e1 + (size_t)m * lde1 + n);
        v0 += f1.x; v1 += f1.y;
    }
    size_t o = (size_t)m * ldc + n;
    if (Cf)  *(float2*)(Cf + o) = make_float2(v0, v1);
    if (Chi) *(__half2*)(Chi + o) = __floats2half2_rn(v0, v1);
}

// ---------------- GEMM variant A: BM=128, BN=64 ----------------
#define APL (128*ASTR)
#define BPL (64*ASTR)
#define STG (APL + BPL)
#define SMEM_BYTES (NSTAGE*STG*2)

__global__ void __launch_bounds__(256, 2) gemm_f16(
    const __half* __restrict__ Ahi, int lda,
    const __half* __restrict__ Whi, int ldb, int wstride,
    float* Cf, __half* Chi, int ldc,
    int4 Ms, int4 rowoffs, int N, int K,
    const float* bias, int bstride, int mode,
    const float* e1, int lde1, const __half* e2h, int lde2)
{
    extern __shared__ __align__(16) __half sm[];
    const int z = blockIdx.z;
    const int M      = (z == 0) ? Ms.x      : ((z == 1) ? Ms.y      : Ms.z);
    const int rowoff = (z == 0) ? rowoffs.x : ((z == 1) ? rowoffs.y : rowoffs.z);
    const int m0 = blockIdx.y * 128;
    if (m0 >= M) return;
    const int n0 = blockIdx.x * 64;

    const int tid = threadIdx.x, lane = tid & 31, wid = tid >> 5;
    const int wm = wid & 3, wn = wid >> 2;

    const __half* Ah = Ahi + (size_t)rowoff * lda;
    const __half* Wh = Whi + (size_t)z * wstride;

    const int arow = tid >> 1, acol = (tid & 1) * 16;
    const int brow = tid >> 2, bcol = (tid & 3) * 8;
    const bool bv = (n0 + brow) < N;

    const __half* agh = Ah + (size_t)(m0 + arow) * lda + acol;
    const __half* bgh = Wh + (size_t)(n0 + brow) * ldb + bcol;

    unsigned int sbase = (unsigned int)__cvta_generic_to_shared(sm);
    const int a_dst = arow * ASTR + acol;
    const int b_dst = brow * ASTR + bcol;

    float acc[2][4][4];
    #pragma unroll
    for (int i = 0; i < 2; i++)
        #pragma unroll
        for (int j = 0; j < 4; j++)
            #pragma unroll
            for (int r = 0; r < 4; r++) acc[i][j][r] = 0.0f;

    const int aoff = (wm * 32 + (lane & 15)) * ASTR + (lane >> 4) * 8;
    const int boff = (wn * 32 + ((lane >> 4) << 3) + (lane & 7)) * ASTR
                   + ((lane >> 3) & 1) * 8;

    const int nk = K / 32;

    auto issue = [&](int s) {
        int k0 = s * 32;
        unsigned int st = sbase + (unsigned int)(s % NSTAGE) * (STG * 2);
        cp16(st + (a_dst) * 2,       agh + k0,     true);
        cp16(st + (a_dst + 8) * 2,   agh + k0 + 8, true);
        cp16(st + (APL + b_dst) * 2, bgh + k0,     bv);
    };

    #pragma unroll
    for (int s = 0; s < NSTAGE - 1; s++) {
        if (s < nk) issue(s);
        asm volatile("cp.async.commit_group;\n");
    }

    for (int it = 0; it < nk; it++) {
        asm volatile("cp.async.wait_group %0;\n" :: "n"(NSTAGE - 2));
        __syncthreads();

        int pf = it + NSTAGE - 1;
        if (pf < nk) issue(pf);
        asm volatile("cp.async.commit_group;\n");

        const __half* st = sm + (it % NSTAGE) * STG;
        #pragma unroll
        for (int k16 = 0; k16 < 2; k16++) {
            unsigned int ahif[8];
            unsigned int bhif[8];
            const __half* pa = st + aoff + k16 * 16;
            ldm_x4(&ahif[0], pa);
            ldm_x4(&ahif[4], pa + 16 * ASTR);
            const __half* pb = st + APL + boff + k16 * 16;
            ldm_x4(&bhif[0], pb);
            ldm_x4(&bhif[4], pb + 16 * ASTR);
            #pragma unroll
            for (int mi = 0; mi < 2; mi++) {
                #pragma unroll
                for (int ni = 0; ni < 4; ni++) {
                    mma16816(acc[mi][ni], &ahif[mi * 4], &bhif[ni * 2]);
                }
            }
        }
    }

    #pragma unroll
    for (int mi = 0; mi < 2; mi++) {
        #pragma unroll
        for (int ni = 0; ni < 4; ni++) {
            int mb = m0 + wm * 32 + mi * 16 + (lane >> 2);
            int n  = n0 + wn * 32 + ni * 8 + (lane & 3) * 2;
            if (n >= N) continue;
            #pragma unroll
            for (int r2 = 0; r2 < 2; r2++) {
                int m = rowoff + mb + r2 * 8;
                epi_pair(acc[mi][ni][r2*2], acc[mi][ni][r2*2+1], m, n, z,
                         Cf, Chi, ldc, bias, bstride, mode, e1, lde1, e2h, lde2);
            }
        }
    }
}

// ---------------- GEMM variant B: BM=64, BN=64 (for low-grid GEMMs) ----------------
#define APL64 (64*ASTR)
#define STG64 (2*APL64)                 // A plane + B plane, both 64 rows
#define SMEM64_BYTES (NSTAGE*STG64*2)   // 51200

__global__ void __launch_bounds__(256, 3) gemm_f16_64(
    const __half* __restrict__ Ahi, int lda,
    const __half* __restrict__ Whi, int ldb, int wstride,
    float* Cf, __half* Chi, int ldc,
    int4 Ms, int4 rowoffs, int N, int K,
    const float* bias, int bstride, int mode,
    const float* e1, int lde1, const __half* e2h, int lde2)
{
    extern __shared__ __align__(16) __half sm[];
    const int z = blockIdx.z;
    const int M      = (z == 0) ? Ms.x      : ((z == 1) ? Ms.y      : Ms.z);
    const int rowoff = (z == 0) ? rowoffs.x : ((z == 1) ? rowoffs.y : rowoffs.z);
    const int m0 = blockIdx.y * 64;
    if (m0 >= M) return;
    const int n0 = blockIdx.x * 64;

    const int tid = threadIdx.x, lane = tid & 31, wid = tid >> 5;
    const int wm = wid & 1, wn = wid >> 1;     // 2 m-warps x 4 n-warps

    const __half* Ah = Ahi + (size_t)rowoff * lda;
    const __half* Wh = Whi + (size_t)z * wstride;

    const int arow = tid >> 2, acol = (tid & 3) * 8;   // 64 rows x 32 cols, 1 cp16/thread
    const bool bv = (n0 + arow) < N;

    const __half* agh = Ah + (size_t)(m0 + arow) * lda + acol;
    const __half* bgh = Wh + (size_t)(n0 + arow) * ldb + acol;

    unsigned int sbase = (unsigned int)__cvta_generic_to_shared(sm);
    const int s_dst = arow * ASTR + acol;

    float acc[2][2][4];
    #pragma unroll
    for (int i = 0; i < 2; i++)
        #pragma unroll
        for (int j = 0; j < 2; j++)
            #pragma unroll
            for (int r = 0; r < 4; r++) acc[i][j][r] = 0.0f;

    const int aoff = (wm * 32 + (lane & 15)) * ASTR + (lane >> 4) * 8;
    const int boff = (wn * 16 + ((lane >> 4) << 3) + (lane & 7)) * ASTR
                   + ((lane >> 3) & 1) * 8;

    const int nk = K / 32;

    auto issue = [&](int s) {
        int k0 = s * 32;
        unsigned int st = sbase + (unsigned int)(s % NSTAGE) * (STG64 * 2);
        cp16(st + (s_dst) * 2,           agh + k0, true);
        cp16(st + (APL64 + s_dst) * 2,   bgh + k0, bv);
    };

    #pragma unroll
    for (int s = 0; s < NSTAGE - 1; s++) {
        if (s < nk) issue(s);
        asm volatile("cp.async.commit_group;\n");
    }

    for (int it = 0; it < nk; it++) {
        asm volatile("cp.async.wait_group %0;\n" :: "n"(NSTAGE - 2));
        __syncthreads();

        int pf = it + NSTAGE - 1;
        if (pf < nk) issue(pf);
        asm volatile("cp.async.commit_group;\n");

        const __half* st = sm + (it % NSTAGE) * STG64;
        #pragma unroll
        for (int k16 = 0; k16 < 2; k16++) {
            unsigned int ahif[8];
            unsigned int bhif[4];
            const __half* pa = st + aoff + k16 * 16;
            ldm_x4(&ahif[0], pa);
            ldm_x4(&ahif[4], pa + 16 * ASTR);
            const __half* pb = st + APL64 + boff + k16 * 16;
            ldm_x4(&bhif[0], pb);
            #pragma unroll
            for (int mi = 0; mi < 2; mi++) {
                #pragma unroll
                for (int ni = 0; ni < 2; ni++) {
                    mma16816(acc[mi][ni], &ahif[mi * 4], &bhif[ni * 2]);
                }
            }
        }
    }

    #pragma unroll
    for (int mi = 0; mi < 2; mi++) {
        #pragma unroll
        for (int ni = 0; ni < 2; ni++) {
            int mb = m0 + wm * 32 + mi * 16 + (lane >> 2);
            int n  = n0 + wn * 16 + ni * 8 + (lane & 3) * 2;
            if (n >= N) continue;
            #pragma unroll
            for (int r2 = 0; r2 < 2; r2++) {
                int m = rowoff + mb + r2 * 8;
                epi_pair(acc[mi][ni][r2*2], acc[mi][ni][r2*2+1], m, n, z,
                         Cf, Chi, ldc, bias, bstride, mode, e1, lde1, e2h, lde2);
            }
        }
    }
}

// ---------------- downsample (both scales, one launch; fp16, half2) ----------------
__global__ void down_batched()
{
    int z = blockIdx.y + 1;
    int Tout = TLEN >> z;
    int S = 1 << z;
    float invS = 1.0f / S;
    int total = NB * Tout * (DIN / 2);
    int idx = blockIdx.x * blockDim.x + threadIdx.x;
    if (idx >= total) return;
    int d2 = idx & (DIN/2 - 1);
    int t  = (idx / (DIN/2)) % Tout;
    int b  = idx / (Tout * (DIN/2));
    const __half* p = g_xzH + (size_t)(b * TLEN + t * S) * (2 * DIN) + d2 * 2;
    float sx = 0.f, sy = 0.f;
    #pragma unroll 4
    for (int r = 0; r < S; r++) {
        float2 a = __half22float2(*(const __half2*)(p + (size_t)r * 2 * DIN));
        sx += a.x; sy += a.y;
    }
    __half* dst = (z == 1) ? g_xs1H : g_xs2H;
    *(__half2*)(dst + (size_t)idx * 2) = __floats2half2_rn(sx * invS, sy * invS);
}

// ---------------- depthwise causal conv, temporal-blocked x4, half2 channels ----------------
__global__ void conv_batched(const float* __restrict__ cw,
                             const float* __restrict__ cb)
{
    int z = blockIdx.y;
    int Tl = TLEN >> z;
    int T4 = Tl >> 2;
    int total = NB * T4 * (DIN / 2);
    int idx = blockIdx.x * blockDim.x + threadIdx.x;
    if (idx >= total) return;
    const __half* xin = (z == 0) ? g_xzH : ((z == 1) ? g_xs1H : g_xs2H);
    int ldx = (z == 0) ? 2 * DIN : DIN;
    size_t roff = (z == 0) ? 0 : ((z == 1) ? (size_t)R0 * DIN : (size_t)(R0 + R1) * DIN);

    int d2 = idx & (DIN/2 - 1);
    int t4 = (idx / (DIN/2)) % T4;
    int b  = idx / (T4 * (DIN/2));
    int d  = d2 * 2;
    int t0 = t4 * 4;

    const float4 w0 = *(const float4*)(cw + (size_t)z * DIN * 4 + d * 4);
    const float4 w1 = *(const float4*)(cw + (size_t)z * DIN * 4 + d * 4 + 4);
    const float2 bi = *(const float2*)(cb + (size_t)z * DIN + d);
    float wa[4]; wa[0]=w0.x; wa[1]=w0.y; wa[2]=w0.z; wa[3]=w0.w;
    float wb[4]; wb[0]=w1.x; wb[1]=w1.y; wb[2]=w1.z; wb[3]=w1.w;

    const __half* base = xin + (size_t)(b * Tl) * ldx + d;
    float2 in[7];
    #pragma unroll
    for (int k = 0; k < 7; k++) {
        int tt = t0 + k - 3;
        in[k] = (tt >= 0)
              ? __half22float2(*(const __half2*)(base + (size_t)tt * ldx))
              : make_float2(0.f, 0.f);
    }

    __half* outp = g_xcH + roff + (size_t)(b * Tl + t0) * DIN + d;
    #pragma unroll
    for (int q = 0; q < 4; q++) {
        float ax = bi.x, ay = bi.y;
        #pragma unroll
        for (int k = 0; k < 4; k++) {
            float2 v = in[q + k];
            ax = fmaf(wa[k], v.x, ax);
            ay = fmaf(wb[k], v.y, ay);
        }
        *(__half2*)(outp + (size_t)q * DIN) = __floats2half2_rn(siluf_(ax), siluf_(ay));
    }
}

// ---------------- selective scan: 2 states/thread, 32 channels/block ----------------
__global__ void scan_batched(const float* __restrict__ A_log,
                             const float* __restrict__ Dp)
{
    const int z = blockIdx.y;
    const int Tl = TLEN >> z;
    const size_t roff  = (z == 0) ? 0 : ((z == 1) ? (size_t)R0 : (size_t)(R0 + R1));
    const __half* xc   = g_xcH + roff * DIN;
    const float*  proj = g_proj + roff * NPROJ;
    const __half* dt   = g_dtH + roff * DIN;
    float*        y    = g_y   + roff * DIN;
    const float*  Al   = A_log + z * DIN * DSTATE;
    const float*  Dz   = Dp + z * DIN;

    const int sg   = threadIdx.x & 7;
    const int dloc = threadIdx.x >> 3;
    const int b    = blockIdx.x >> 5;
    const int d0   = (blockIdx.x & 31) * 32;
    const int d    = d0 + dloc;
    const int s0   = sg * 2;

    __shared__ float2 s_ddx[64][32];
    __shared__ float2 s_BC [64][16];
    __shared__ float  s_xc [64][32];

    const float Aj0 = -expf(Al[d * 16 + s0])     * LOG2E;
    const float Aj1 = -expf(Al[d * 16 + s0 + 1]) * LOG2E;
    const float Dv  = Dz[d];
    float h0 = 0.0f, h1 = 0.0f;

    for (int t0 = 0; t0 < Tl; t0 += 64) {
        for (int i = threadIdx.x; i < 64 * 16; i += 256) {
            int tt = i >> 4;
            int dl = (i & 15) * 2;
            size_t rbase = (size_t)(b * Tl + t0 + tt);
            float2 dtv2 = __half22float2(*(const __half2*)(dt + rbase * DIN + d0 + dl));
            float2 xcv2 = __half22float2(*(const __half2*)(xc + rbase * DIN + d0 + dl));
            float sp0 = softplusf_(dtv2.x), sp1 = softplusf_(dtv2.y);
            s_ddx[tt][dl]   = make_float2(sp0, sp0 * xcv2.x);
            s_ddx[tt][dl+1] = make_float2(sp1, sp1 * xcv2.y);
            s_xc[tt][dl]   = xcv2.x;
            s_xc[tt][dl+1] = xcv2.y;
        }
        for (int i = threadIdx.x; i < 64 * 8; i += 256) {
            int tt = i >> 3;
            int sl = (i & 7) * 2;
            size_t rbase = (size_t)(b * Tl + t0 + tt);
            const float* pr = proj + rbase * NPROJ;
            float2 Bv = *(const float2*)(pr + DTRANK + sl);
            float2 Cv = *(const float2*)(pr + DTRANK + DSTATE + sl);
            s_BC[tt][sl]   = make_float2(Bv.x, Cv.x);
            s_BC[tt][sl+1] = make_float2(Bv.y, Cv.y);
        }
        __syncthreads();
        #pragma unroll 4
        for (int tt = 0; tt < 64; tt++) {
            float2 ddx = s_ddx[tt][dloc];
            float4 bc  = *(const float4*)&s_BC[tt][s0];
            float dA0  = fmaxf(ex2a(ddx.x * Aj0), 1e-38f);
            float dA1  = fmaxf(ex2a(ddx.x * Aj1), 1e-38f);
            float dBx0 = fmaxf(ddx.y * bc.x, 1e-38f);
            float dBx1 = fmaxf(ddx.y * bc.z, 1e-38f);
            h0 = fmaf(dA0, h0, dBx0);
            h1 = fmaf(dA1, h1, dBx1);
            float part = fmaf(bc.w, h1, bc.y * h0);
            part += __shfl_xor_sync(0xffffffffu, part, 4);
            part += __shfl_xor_sync(0xffffffffu, part, 2);
            part += __shfl_xor_sync(0xffffffffu, part, 1);
            if (sg == 0)
                y[(size_t)(b * Tl + t0 + tt) * DIN + d] = fmaf(Dv, s_xc[tt][dloc], part);
        }
        __syncthreads();
    }
}

// ---------------- fuse (float4-vectorized, includes scale-weight softmax) ----------------
__global__ void fuse_kernel(const float* __restrict__ sw)
{
    int idx4 = blockIdx.x * blockDim.x + threadIdx.x;
    int d4 = idx4 & (DIN/4 - 1);
    int t  = (idx4 / (DIN/4)) & (TLEN - 1);
    int b  = idx4 / ((DIN/4) * TLEN);
    int d  = d4 * 4;

    float a = sw[0], bb = sw[1], c = sw[2];
    float mx = fmaxf(a, fmaxf(bb, c));
    float ea = ex2a((a - mx) * LOG2E);
    float eb = ex2a((bb - mx) * LOG2E);
    float ec = ex2a((c - mx) * LOG2E);
    float inv = __fdividef(1.0f, ea + eb + ec);
    ea *= inv; eb *= inv; ec *= inv;

    size_t i0 = (size_t)(b * TLEN + t) * DIN + d;
    size_t i1 = (size_t)R0 * DIN + (size_t)(b * (TLEN/2) + (t >> 1)) * DIN + d;
    size_t i2 = (size_t)(R0 + R1) * DIN + (size_t)(b * (TLEN/4) + (t >> 2)) * DIN + d;
    float4 o0 = *(const float4*)(g_y + i0);
    float4 o1 = *(const float4*)(g_y + i1);
    float4 o2 = *(const float4*)(g_y + i2);

    float4 f;
    f.x = ea*o0.x + eb*o1.x + ec*o2.x;
    f.y = ea*o0.y + eb*o1.y + ec*o2.y;
    f.z = ea*o0.z + eb*o1.z + ec*o2.z;
    f.w = ea*o0.w + eb*o1.w + ec*o2.w;
    *(float4*)(g_fused + i0) = f;

    const float th = 1.0f / 3.0f;
    *(__half2*)(g_cth + i0)     = __floats2half2_rn((o0.x+o1.x+o2.x)*th, (o0.y+o1.y+o2.y)*th);
    *(__half2*)(g_cth + i0 + 2) = __floats2half2_rn((o0.z+o1.z+o2.z)*th, (o0.w+o1.w+o2.w)*th);
}

// ---------------- LayerNorm ----------------
__global__ void ln_kernel(const float* __restrict__ gamma,
                          const float* __restrict__ beta,
                          float* __restrict__ out)
{
    int row = blockIdx.x;
    int tid = threadIdx.x;
    const float* r = g_pre + (size_t)row * DMODEL;
    float v1 = r[tid], v2 = r[tid + 256];
    float s  = v1 + v2;
    float q  = v1 * v1 + v2 * v2;
    #pragma unroll
    for (int o = 16; o > 0; o >>= 1) {
        s += __shfl_xor_sync(0xffffffffu, s, o);
        q += __shfl_xor_sync(0xffffffffu, q, o);
    }
    __shared__ float sh[8], sh2[8];
    int wid = tid >> 5, lane = tid & 31;
    if (lane == 0) { sh[wid] = s; sh2[wid] = q; }
    __syncthreads();
    if (tid == 0) {
        float ts = 0.f, tq = 0.f;
        #pragma unroll
        for (int i = 0; i < 8; i++) { ts += sh[i]; tq += sh2[i]; }
        sh[0] = ts; sh2[0] = tq;
    }
    __syncthreads();
    float mu  = sh[0] * (1.0f / DMODEL);
    float var = sh2[0] * (1.0f / DMODEL) - mu * mu;
    float inv = rsqrtf(var + 1e-5f);
    float* o = out + (size_t)row * DMODEL;
    o[tid]       = (v1 - mu) * inv * gamma[tid]       + beta[tid];
    o[tid + 256] = (v2 - mu) * inv * gamma[tid + 256] + beta[tid + 256];
}

// ---------------- driver ----------------
extern "C" void kernel_launch(void* const* d_in, const int* in_sizes, int n_in,
                              void* d_out, int out_size)
{
    const float* x        = (const float*)d_in[0];
    const float* in_proj  = (const float*)d_in[1];
    const float* conv_w   = (const float*)d_in[2];
    const float* conv_b   = (const float*)d_in[3];
    const float* xproj_w  = (const float*)d_in[4];
    const float* dtproj_w = (const float*)d_in[5];
    const float* dtproj_b = (const float*)d_in[6];
    const float* A_log    = (const float*)d_in[7];
    const float* D_p      = (const float*)d_in[8];
    const float* sw       = (const float*)d_in[9];
    const float* cg_w1    = (const float*)d_in[10];
    const float* cg_w2    = (const float*)d_in[11];
    const float* out_w    = (const float*)d_in[12];
    const float* ln_g     = (const float*)d_in[13];
    const float* ln_b     = (const float*)d_in[14];
    float* out            = (float*)d_out;

    static bool attr_set = false;
    if (!attr_set) {
        cudaFuncSetAttribute(gemm_f16, cudaFuncAttributeMaxDynamicSharedMemorySize,
                             SMEM_BYTES);
        cudaFuncSetAttribute(gemm_f16_64, cudaFuncAttributeMaxDynamicSharedMemorySize,
                             SMEM64_BYTES);
        attr_set = true;
    }

    float *proj, *fused, *pre;
    __half *xh,*wih,*xph,*dwh,*c1h,*c2h,*owh;
    __half *xzH,*xcH,*dtH,*pH,*cth,*h1h,*ach;
    cudaGetSymbolAddress((void**)&proj, g_proj);
    cudaGetSymbolAddress((void**)&fused,g_fused);
    cudaGetSymbolAddress((void**)&pre,  g_pre);
    cudaGetSymbolAddress((void**)&xh,  g_xh);
    cudaGetSymbolAddress((void**)&wih, g_wih);
    cudaGetSymbolAddress((void**)&xph, g_xph);
    cudaGetSymbolAddress((void**)&dwh, g_dwh);
    cudaGetSymbolAddress((void**)&c1h, g_c1h);
    cudaGetSymbolAddress((void**)&c2h, g_c2h);
    cudaGetSymbolAddress((void**)&owh, g_owh);
    cudaGetSymbolAddress((void**)&xzH, g_xzH);
    cudaGetSymbolAddress((void**)&xcH, g_xcH);
    cudaGetSymbolAddress((void**)&dtH, g_dtH);
    cudaGetSymbolAddress((void**)&pH,  g_pH);
    cudaGetSymbolAddress((void**)&cth, g_cth);
    cudaGetSymbolAddress((void**)&h1h, g_h1h);
    cudaGetSymbolAddress((void**)&ach, g_ach);

    const int4 M1   = make_int4(R0, 0, 0, 0);
    const int4 OFF0 = make_int4(0, 0, 0, 0);
    const int4 M3   = make_int4(R0, R1, R2, 0);
    const int4 OFF3 = make_int4(0, R0, R0 + R1, 0);

    // 0. convert inputs + weights to fp16 planes
    split_all<<<(CU6/4 + 255)/256, 256>>>(x, in_proj, xproj_w, dtproj_w,
                                          cg_w1, cg_w2, out_w);

    // 1. in_proj -> fp16 xz   (BM=128 variant; 512 blocks)
    gemm_f16<<<dim3(32, 16, 1), 256, SMEM_BYTES>>>(
        xh, DMODEL, wih, DMODEL, 0,
        nullptr, xzH, 2*DIN, M1, OFF0, 2*DIN, DMODEL,
        nullptr, 0, 0, nullptr, 0, nullptr, 0);

    // 2. downsample (both scales, one launch)
    down_batched<<<dim3((R1*DIN/2 + 255)/256, 2), 256>>>();

    // 3. conv (temporal-blocked x4, half2 channels)
    conv_batched<<<dim3((R0*DIN/8 + 255)/256, 3), 256>>>(conv_w, conv_b);

    // 4. xproj (BM=64: 192 blocks): N=96, K=1024
    gemm_f16_64<<<dim3(2, 32, 3), 256, SMEM64_BYTES>>>(
        xcH, DIN, xph, DIN, NPROJ*DIN,
        proj, pH, NPROJ, M3, OFF3, NPROJ, DIN,
        nullptr, 0, 0, nullptr, 0, nullptr, 0);

    // 5. dtproj (BM=128: 768 blocks): N=1024, K=64 (+bias)
    gemm_f16<<<dim3(16, 16, 3), 256, SMEM_BYTES>>>(
        pH, NPROJ, dwh, DTRANK, DIN*DTRANK,
        nullptr, dtH, DIN, M3, OFF3, DIN, DTRANK,
        dtproj_b, DIN, 1, nullptr, 0, nullptr, 0);

    // 6. selective scan (2 states/thread, 32 ch/block)
    scan_batched<<<dim3(NB*DIN/32, 3), 256>>>(A_log, D_p);

    // 7. fuse (+softmax)
    fuse_kernel<<<(R0*DIN/4)/256, 256>>>(sw);

    // 8. context gate (BM=64: 256 / 512 blocks)
    gemm_f16_64<<<dim3(8, 32, 1), 256, SMEM64_BYTES>>>(
        cth, DIN, c1h, DIN, 0,
        nullptr, h1h, DIN/2, M1, OFF0, DIN/2, DIN,
        nullptr, 0, 2, nullptr, 0, nullptr, 0);
    gemm_f16_64<<<dim3(16, 32, 1), 256, SMEM64_BYTES>>>(
        h1h, DIN/2, c2h, DIN/2, 0,
        nullptr, ach, DIN, M1, OFF0, DIN, DIN/2,
        nullptr, 0, 3, fused, DIN, xzH + DIN, 2*DIN);

    // 9. out_proj + residual (BM=64: 256 blocks)
    gemm_f16_64<<<dim3(8, 32, 1), 256, SMEM64_BYTES>>>(
        ach, DIN, owh, DIN, 0,
        pre, nullptr, DMODEL, M1, OFF0, DMODEL, DIN,
        nullptr, 0, 4, x, DMODEL, nullptr, 0);

    // 10. LayerNorm
    ln_kernel<<<R0, 256>>>(ln_g, ln_b, out);
}